// round 4
// baseline (speedup 1.0000x reference)
#include <cuda_runtime.h>
#include <cuda_bf16.h>
#include <cuda_fp16.h>
#include <cstdint>

// Problem constants
#define N_ 32768
#define D_ 512
#define Q_ 4
#define K_ 2048

// GEMM tiling
#define BM 128
#define BN 128
#define BK 32
#define NIT (D_ / BK)   // 16

// ---------------- device scratch ----------------
__device__ float g_res[N_ * D_];                    // fp32 residual (64 MB)
__device__ __nv_bfloat16 g_resh[N_ * D_];           // bf16 residual (32 MB)
__device__ __nv_bfloat16 g_cbh[Q_ * K_ * D_];       // bf16 codebooks (8 MB)
__device__ __half g_disth[(size_t)N_ * K_];         // coarse distances fp16 (128 MB)
__device__ float g_rn2[N_];
__device__ float g_en2[Q_ * K_];
__device__ unsigned long long g_key[N_];            // coarse packed (dist_bits<<32)|k
__device__ double g_lossp[Q_ * 64];

// ---------------- PTX helpers ----------------
__device__ __forceinline__ void cp_async16(uint32_t saddr, const void* gaddr) {
    asm volatile("cp.async.cg.shared.global [%0], [%1], 16;" :: "r"(saddr), "l"(gaddr));
}
#define CP_COMMIT() asm volatile("cp.async.commit_group;")
#define CP_WAIT1()  asm volatile("cp.async.wait_group 1;")

__device__ __forceinline__ void ldsm4(uint32_t& r0, uint32_t& r1, uint32_t& r2, uint32_t& r3,
                                      uint32_t addr) {
    asm volatile("ldmatrix.sync.aligned.m8n8.x4.shared.b16 {%0,%1,%2,%3}, [%4];"
                 : "=r"(r0), "=r"(r1), "=r"(r2), "=r"(r3) : "r"(addr));
}
__device__ __forceinline__ void mma16816(float* c, const uint32_t* a, const uint32_t* b) {
    asm volatile(
        "mma.sync.aligned.m16n8k16.row.col.f32.bf16.bf16.f32 "
        "{%0,%1,%2,%3}, {%4,%5,%6,%7}, {%8,%9}, {%0,%1,%2,%3};"
        : "+f"(c[0]), "+f"(c[1]), "+f"(c[2]), "+f"(c[3])
        : "r"(a[0]), "r"(a[1]), "r"(a[2]), "r"(a[3]), "r"(b[0]), "r"(b[1]));
}

// ---------------- init ----------------
__global__ void init_kernel(const float* __restrict__ x, float* __restrict__ xq) {
    int i = blockIdx.x * blockDim.x + threadIdx.x;
    g_res[i] = x[i];
    xq[i] = 0.0f;
    if (i < Q_ * 64) g_lossp[i] = 0.0;
}

// ---------------- codebook norms (identical arithmetic to R1) ----------------
__global__ void cbnorm_kernel(const float* __restrict__ cbs) {
    int w = (blockIdx.x * blockDim.x + threadIdx.x) >> 5;
    int lane = threadIdx.x & 31;
    if (w >= Q_ * K_) return;
    const float4* row = reinterpret_cast<const float4*>(cbs + (size_t)w * D_);
    float ss = 0.0f;
#pragma unroll
    for (int i = 0; i < 4; i++) {
        float4 v = row[lane + i * 32];
        ss += v.x * v.x + v.y * v.y + v.z * v.z + v.w * v.w;
    }
#pragma unroll
    for (int off = 16; off > 0; off >>= 1)
        ss += __shfl_xor_sync(0xFFFFFFFFu, ss, off);
    if (lane == 0) g_en2[w] = ss;
}

// ---------------- codebook bf16 conversion ----------------
__global__ void cbconv_kernel(const float* __restrict__ cbs) {
    int t = blockIdx.x * blockDim.x + threadIdx.x;
    float4 v = reinterpret_cast<const float4*>(cbs)[t];
    __nv_bfloat162* o = reinterpret_cast<__nv_bfloat162*>(g_cbh);
    o[t * 2 + 0] = __nv_bfloat162(__float2bfloat16_rn(v.x), __float2bfloat16_rn(v.y));
    o[t * 2 + 1] = __nv_bfloat162(__float2bfloat16_rn(v.z), __float2bfloat16_rn(v.w));
}

// ---------------- per-stage prep: rn2 (R1 order) + bf16 residual + key reset
//                  + loss accumulation for the PREVIOUS stage (rn2 == ||r_new||^2)
__global__ void prep_kernel(int s) {
    int w = (blockIdx.x * blockDim.x + threadIdx.x) >> 5;
    int lane = threadIdx.x & 31;
    if (w >= N_) return;
    const float4* row = reinterpret_cast<const float4*>(g_res + (size_t)w * D_);
    uint2* orow = reinterpret_cast<uint2*>(g_resh + (size_t)w * D_);
    float ss = 0.0f;
#pragma unroll
    for (int i = 0; i < 4; i++) {
        float4 v = row[lane + i * 32];
        ss += v.x * v.x + v.y * v.y + v.z * v.z + v.w * v.w;
        __nv_bfloat162 lo(__float2bfloat16_rn(v.x), __float2bfloat16_rn(v.y));
        __nv_bfloat162 hi(__float2bfloat16_rn(v.z), __float2bfloat16_rn(v.w));
        uint2 pk;
        pk.x = *reinterpret_cast<uint32_t*>(&lo);
        pk.y = *reinterpret_cast<uint32_t*>(&hi);
        orow[lane + i * 32] = pk;
    }
#pragma unroll
    for (int off = 16; off > 0; off >>= 1)
        ss += __shfl_xor_sync(0xFFFFFFFFu, ss, off);
    if (lane == 0) {
        g_rn2[w] = ss;
        g_key[w] = ~0ull;
        if (s > 0) atomicAdd(&g_lossp[(s - 1) * 64 + (w & 63)], (double)ss);
    }
}

// ---------------- HMMA bf16 coarse distance GEMM + coarse argmin ----------------
// grid (N_/BM, K_/BN), 256 threads = 8 warps (4m x 2n), warp tile 32x64.
__global__ __launch_bounds__(256, 2)
void gemm_dist_kernel(int q) {
    __shared__ alignas(128) __nv_bfloat16 sA[2][BM * BK];   // 8 KB each
    __shared__ alignas(128) __nv_bfloat16 sB[2][BN * BK];
    __shared__ float s_en2[BN];
    __shared__ float s_rn2[BM];
    __shared__ unsigned long long rowKey[BM];

    const int tid = threadIdx.x;
    const int wid = tid >> 5;
    const int lane = tid & 31;
    const int warp_m = wid >> 1;     // 0..3
    const int warp_n = wid & 1;      // 0..1
    const int gid = lane >> 2;       // groupID 0..7
    const int tig = lane & 3;

    const int nBase = blockIdx.x * BM;
    const int kBase = blockIdx.y * BN;

    if (tid < 128) {
        s_en2[tid] = g_en2[q * K_ + kBase + tid];
        s_rn2[tid] = g_rn2[nBase + tid];
        rowKey[tid] = ~0ull;
    }

    const __nv_bfloat16* gA = g_resh;
    const __nv_bfloat16* gB = g_cbh + (size_t)q * K_ * D_;

    uint32_t saA[2], saB[2];
    saA[0] = (uint32_t)__cvta_generic_to_shared(&sA[0][0]);
    saA[1] = (uint32_t)__cvta_generic_to_shared(&sA[1][0]);
    saB[0] = (uint32_t)__cvta_generic_to_shared(&sB[0][0]);
    saB[1] = (uint32_t)__cvta_generic_to_shared(&sB[1][0]);

    float c[2][8][4];
#pragma unroll
    for (int i = 0; i < 2; i++)
#pragma unroll
        for (int j = 0; j < 8; j++)
#pragma unroll
            for (int v = 0; v < 4; v++) c[i][j][v] = 0.0f;

    auto load_tiles = [&](int buf, int d0) {
#pragma unroll
        for (int u = 0; u < 2; u++) {
            int cidx = tid + 256 * u;
            int r = cidx >> 2, ch = cidx & 3;
            uint32_t off = (uint32_t)(r * 64 + ((ch ^ (r & 3)) << 4));
            cp_async16(saA[buf] + off, gA + (size_t)(nBase + r) * D_ + d0 + ch * 8);
            cp_async16(saB[buf] + off, gB + (size_t)(kBase + r) * D_ + d0 + ch * 8);
        }
    };

    load_tiles(0, 0);
    CP_COMMIT();

    for (int it = 0; it < NIT; it++) {
        int buf = it & 1;
        if (it + 1 < NIT) load_tiles(buf ^ 1, (it + 1) * BK);
        CP_COMMIT();
        CP_WAIT1();
        __syncthreads();

#pragma unroll
        for (int kk = 0; kk < 2; kk++) {
            uint32_t a[2][4], b[8][2];
#pragma unroll
            for (int i = 0; i < 2; i++) {
                int row = warp_m * 32 + i * 16 + (lane & 7) + ((lane >> 3) & 1) * 8;
                int ch = kk * 2 + (lane >> 4);
                uint32_t addr = saA[buf] + (uint32_t)(row * 64 + ((ch ^ (row & 3)) << 4));
                ldsm4(a[i][0], a[i][1], a[i][2], a[i][3], addr);
            }
#pragma unroll
            for (int p = 0; p < 4; p++) {
                int row = warp_n * 64 + p * 16 + (lane & 7) + ((lane >> 4) & 1) * 8;
                int ch = kk * 2 + ((lane >> 3) & 1);
                uint32_t addr = saB[buf] + (uint32_t)(row * 64 + ((ch ^ (row & 3)) << 4));
                ldsm4(b[2 * p][0], b[2 * p][1], b[2 * p + 1][0], b[2 * p + 1][1], addr);
            }
#pragma unroll
            for (int i = 0; i < 2; i++)
#pragma unroll
                for (int j = 0; j < 8; j++)
                    mma16816(c[i][j], a[i], b[j]);
        }
        __syncthreads();
    }

    // ---- epilogue: dist = rn2 + en2 - 2*dot ; store fp16 ; coarse argmin ----
#pragma unroll
    for (int i = 0; i < 2; i++) {
#pragma unroll
        for (int r2 = 0; r2 < 2; r2++) {
            int rowL = warp_m * 32 + i * 16 + gid + r2 * 8;
            float rn2 = s_rn2[rowL];
            unsigned long long best = ~0ull;
            __half* drow = g_disth + (size_t)(nBase + rowL) * K_ + kBase;
#pragma unroll
            for (int j = 0; j < 8; j++) {
                int colL = warp_n * 64 + j * 8 + tig * 2;
                float d0 = rn2 + s_en2[colL] - 2.0f * c[i][j][r2 * 2 + 0];
                float d1 = rn2 + s_en2[colL + 1] - 2.0f * c[i][j][r2 * 2 + 1];
                *reinterpret_cast<__half2*>(drow + colL) = __floats2half2_rn(d0, d1);
                unsigned kg0 = (unsigned)(kBase + colL);
                unsigned long long k0 =
                    ((unsigned long long)__float_as_uint(d0) << 32) | kg0;
                unsigned long long k1 =
                    ((unsigned long long)__float_as_uint(d1) << 32) | (kg0 + 1);
                if (k0 < best) best = k0;
                if (k1 < best) best = k1;
            }
#pragma unroll
            for (int m = 1; m < 4; m <<= 1) {
                unsigned long long o = __shfl_xor_sync(0xFFFFFFFFu, best, m);
                if (o < best) best = o;
            }
            if (tig == 0) atomicMin(&rowKey[rowL], best);
        }
    }
    __syncthreads();
    if (tid < 128) atomicMin(&g_key[nBase + tid], rowKey[tid]);
}

// ---------------- fixup + update (fused) ----------------
// one block per row. Exact rescore replicates R1's sequential fmaf chain bit-for-bit.
__global__ __launch_bounds__(256)
void fixup_update_kernel(const float* __restrict__ cb, float* __restrict__ xq,
                         float* __restrict__ idx_out, int q) {
    __shared__ alignas(16) float sres[D_];
    __shared__ int s_cand[256];
    __shared__ int s_cnt;
    __shared__ unsigned long long s_best;

    const int r = blockIdx.x;
    const int tid = threadIdx.x;

    if (tid == 0) { s_cnt = 0; s_best = ~0ull; }
    float2 rv = reinterpret_cast<const float2*>(g_res + (size_t)r * D_)[tid];
    sres[2 * tid] = rv.x;
    sres[2 * tid + 1] = rv.y;

    unsigned long long ck = g_key[r];
    float thr = __uint_as_float((unsigned)(ck >> 32)) + 64.0f;
    const __half2* drow = reinterpret_cast<const __half2*>(g_disth + (size_t)r * K_);
    __syncthreads();

#pragma unroll
    for (int i = 0; i < 4; i++) {
        float2 f = __half22float2(drow[tid + i * 256]);
        if (f.x < thr) {
            int p = atomicAdd(&s_cnt, 1);
            if (p < 256) s_cand[p] = (tid + i * 256) * 2;
        }
        if (f.y < thr) {
            int p = atomicAdd(&s_cnt, 1);
            if (p < 256) s_cand[p] = (tid + i * 256) * 2 + 1;
        }
    }
    __syncthreads();
    int nc = min(s_cnt, 256);
    float rn2 = g_rn2[r];
    // one thread per candidate: strict sequential fmaf chain over d = 0..511
    // (bit-identical to the R1 kernel's accumulation order)
    for (int ci = tid; ci < nc; ci += 256) {
        int k = s_cand[ci];
        const float* crow = cb + (size_t)k * D_;
        float dot = 0.0f;
#pragma unroll 8
        for (int d = 0; d < D_; d++)
            dot = fmaf(sres[d], __ldg(crow + d), dot);
        float dist = (rn2 + g_en2[q * K_ + k]) - 2.0f * dot;
        unsigned long long key =
            ((unsigned long long)__float_as_uint(dist) << 32) | (unsigned)k;
        atomicMin(&s_best, key);
    }
    __syncthreads();
    int kbest = (int)(unsigned)(s_best & 0xFFFFFFFFull);
    if (tid == 0) idx_out[(size_t)r * Q_ + q] = (float)kbest;

    // update: residual, xq (rn2/resh/loss handled by next prep)
    float2 e = reinterpret_cast<const float2*>(cb + (size_t)kbest * D_)[tid];
    reinterpret_cast<float2*>(g_res + (size_t)r * D_)[tid] =
        make_float2(rv.x - e.x, rv.y - e.y);
    float2 xo = reinterpret_cast<float2*>(xq + (size_t)r * D_)[tid];
    reinterpret_cast<float2*>(xq + (size_t)r * D_)[tid] =
        make_float2(xo.x + e.x, xo.y + e.y);
}

// ---------------- finalize mean loss ----------------
__global__ void finalize_kernel(float* __restrict__ loss_out) {
    if (threadIdx.x == 0) {
        double s = 0.0;
        for (int i = 0; i < Q_ * 64; i++) s += g_lossp[i];
        double ml = (s * 1.25 / ((double)N_ * (double)D_)) / (double)Q_;
        *loss_out = (float)ml;
    }
}

// ---------------- launch ----------------
extern "C" void kernel_launch(void* const* d_in, const int* in_sizes, int n_in,
                              void* d_out, int out_size) {
    const float* x = (const float*)d_in[0];
    const float* cbs = (const float*)d_in[1];
    float* out = (float*)d_out;
    float* xq = out;                                  // [N, D]
    float* loss_out = out + (size_t)N_ * D_;          // scalar
    float* idx_out = out + (size_t)N_ * D_ + 1;       // [N, Q] as float

    init_kernel<<<(N_ * D_) / 256, 256>>>(x, xq);
    cbnorm_kernel<<<(Q_ * K_) / 8, 256>>>(cbs);
    cbconv_kernel<<<(Q_ * K_ * D_ / 4) / 256, 256>>>(cbs);

    for (int q = 0; q < Q_; q++) {
        const float* cb = cbs + (size_t)q * K_ * D_;
        prep_kernel<<<N_ / 8, 256>>>(q);
        dim3 grid(N_ / BM, K_ / BN);
        gemm_dist_kernel<<<grid, 256>>>(q);
        fixup_update_kernel<<<N_, 256>>>(cb, xq, idx_out, q);
    }
    prep_kernel<<<N_ / 8, 256>>>(Q_);   // accumulates stage-3 loss from final residual
    finalize_kernel<<<1, 32>>>(loss_out);
}

// round 5
// speedup vs baseline: 1.7886x; 1.7886x over previous
#include <cuda_runtime.h>
#include <cuda_fp16.h>
#include <cstdint>

// Problem constants
#define N_ 32768
#define D_ 512
#define Q_ 4
#define K_ 2048

// GEMM tiling (int8): BK = 64 s8 elements = 64 bytes per row-chunk
#define BM 128
#define BN 128
#define BKI 64
#define NIT (D_ / BKI)   // 8
#define STAGES 3

// ---------------- device scratch ----------------
__device__ float g_res[N_ * D_];                    // fp32 residual (64 MB)
__device__ int8_t g_qres[N_ * D_];                  // int8 residual (16 MB)
__device__ int8_t g_qcb[Q_ * K_ * D_];              // int8 codebooks (4 MB)
__device__ __half g_disth[(size_t)N_ * K_];         // coarse distances fp16 (128 MB)
__device__ float g_rn2[N_];
__device__ float g_sa[N_];                          // residual row scales
__device__ float g_en2[Q_ * K_];
__device__ float g_sb[Q_ * K_];                     // codebook row scales
__device__ unsigned long long g_key[N_];            // coarse packed (dist_bits<<32)|k
__device__ double g_lossp[Q_ * 64];

// ---------------- PTX helpers ----------------
__device__ __forceinline__ void cp_async16(uint32_t saddr, const void* gaddr) {
    asm volatile("cp.async.cg.shared.global [%0], [%1], 16;" :: "r"(saddr), "l"(gaddr));
}
#define CP_COMMIT() asm volatile("cp.async.commit_group;")
#define CP_WAIT1()  asm volatile("cp.async.wait_group 1;")

__device__ __forceinline__ void ldsm4(uint32_t& r0, uint32_t& r1, uint32_t& r2, uint32_t& r3,
                                      uint32_t addr) {
    asm volatile("ldmatrix.sync.aligned.m8n8.x4.shared.b16 {%0,%1,%2,%3}, [%4];"
                 : "=r"(r0), "=r"(r1), "=r"(r2), "=r"(r3) : "r"(addr));
}
__device__ __forceinline__ void mma_s8(int* c, const uint32_t* a, const uint32_t* b) {
    asm volatile(
        "mma.sync.aligned.m16n8k32.row.col.s32.s8.s8.s32 "
        "{%0,%1,%2,%3}, {%4,%5,%6,%7}, {%8,%9}, {%0,%1,%2,%3};"
        : "+r"(c[0]), "+r"(c[1]), "+r"(c[2]), "+r"(c[3])
        : "r"(a[0]), "r"(a[1]), "r"(a[2]), "r"(a[3]), "r"(b[0]), "r"(b[1]));
}

__device__ __forceinline__ int8_t q8(float v, float inv) {
    int t = __float2int_rn(v * inv);
    t = max(-127, min(127, t));
    return (int8_t)t;
}

// ---------------- init: residual = x, xq = 0, losses = 0 ----------------
__global__ void init_kernel(const float* __restrict__ x, float* __restrict__ xq) {
    int i = blockIdx.x * blockDim.x + threadIdx.x;
    g_res[i] = x[i];
    xq[i] = 0.0f;
    if (i < Q_ * 64) g_lossp[i] = 0.0;
}

// ---------------- codebook: en2 (R1 order) + amax + int8 quant, one warp/row ----
__global__ void cbfuse_kernel(const float* __restrict__ cbs) {
    int w = (blockIdx.x * blockDim.x + threadIdx.x) >> 5;
    int lane = threadIdx.x & 31;
    if (w >= Q_ * K_) return;
    const float4* row = reinterpret_cast<const float4*>(cbs + (size_t)w * D_);
    float4 v[4];
    float ss = 0.0f, am = 0.0f;
#pragma unroll
    for (int i = 0; i < 4; i++) {
        v[i] = row[lane + i * 32];
        ss += v[i].x * v[i].x + v[i].y * v[i].y + v[i].z * v[i].z + v[i].w * v[i].w;
        am = fmaxf(am, fmaxf(fmaxf(fabsf(v[i].x), fabsf(v[i].y)),
                             fmaxf(fabsf(v[i].z), fabsf(v[i].w))));
    }
#pragma unroll
    for (int off = 16; off > 0; off >>= 1) {
        ss += __shfl_xor_sync(0xFFFFFFFFu, ss, off);
        am = fmaxf(am, __shfl_xor_sync(0xFFFFFFFFu, am, off));
    }
    float inv = (am > 0.0f) ? 127.0f / am : 0.0f;
    char4* orow = reinterpret_cast<char4*>(g_qcb + (size_t)w * D_);
#pragma unroll
    for (int i = 0; i < 4; i++) {
        char4 c;
        c.x = q8(v[i].x, inv); c.y = q8(v[i].y, inv);
        c.z = q8(v[i].z, inv); c.w = q8(v[i].w, inv);
        orow[lane + i * 32] = c;
    }
    if (lane == 0) { g_en2[w] = ss; g_sb[w] = am / 127.0f; }
}

// ---------------- per-stage prep: rn2 (R1 order) + int8 quant + key reset
//                  + loss accumulation for the PREVIOUS stage ----------------
__global__ void prep_kernel(int s) {
    int w = (blockIdx.x * blockDim.x + threadIdx.x) >> 5;
    int lane = threadIdx.x & 31;
    if (w >= N_) return;
    const float4* row = reinterpret_cast<const float4*>(g_res + (size_t)w * D_);
    float4 v[4];
    float ss = 0.0f, am = 0.0f;
#pragma unroll
    for (int i = 0; i < 4; i++) {
        v[i] = row[lane + i * 32];
        ss += v[i].x * v[i].x + v[i].y * v[i].y + v[i].z * v[i].z + v[i].w * v[i].w;
        am = fmaxf(am, fmaxf(fmaxf(fabsf(v[i].x), fabsf(v[i].y)),
                             fmaxf(fabsf(v[i].z), fabsf(v[i].w))));
    }
#pragma unroll
    for (int off = 16; off > 0; off >>= 1) {
        ss += __shfl_xor_sync(0xFFFFFFFFu, ss, off);
        am = fmaxf(am, __shfl_xor_sync(0xFFFFFFFFu, am, off));
    }
    float inv = (am > 0.0f) ? 127.0f / am : 0.0f;
    char4* orow = reinterpret_cast<char4*>(g_qres + (size_t)w * D_);
#pragma unroll
    for (int i = 0; i < 4; i++) {
        char4 c;
        c.x = q8(v[i].x, inv); c.y = q8(v[i].y, inv);
        c.z = q8(v[i].z, inv); c.w = q8(v[i].w, inv);
        orow[lane + i * 32] = c;
    }
    if (lane == 0) {
        g_rn2[w] = ss;
        g_sa[w] = am / 127.0f;
        g_key[w] = ~0ull;
        if (s > 0) atomicAdd(&g_lossp[(s - 1) * 64 + (w & 63)], (double)ss);
    }
}

// ---------------- int8 coarse distance GEMM + coarse argmin ----------------
// grid (N_/BM, K_/BN), 256 threads = 8 warps (4m x 2n), warp tile 32x64.
__global__ __launch_bounds__(256, 2)
void gemm_dist_kernel(int q) {
    __shared__ alignas(128) int8_t sA[STAGES][BM * BKI];   // 8 KB each
    __shared__ alignas(128) int8_t sB[STAGES][BN * BKI];
    __shared__ float s_en2[BN];
    __shared__ float s_rn2[BM];
    __shared__ float s_sa[BM];
    __shared__ float s_sb[BN];
    __shared__ unsigned long long rowKey[BM];

    const int tid = threadIdx.x;
    const int wid = tid >> 5;
    const int lane = tid & 31;
    const int warp_m = wid >> 1;     // 0..3
    const int warp_n = wid & 1;      // 0..1
    const int gid = lane >> 2;       // 0..7
    const int tig = lane & 3;

    const int nBase = blockIdx.x * BM;
    const int kBase = blockIdx.y * BN;

    if (tid < 128) {
        s_en2[tid] = g_en2[q * K_ + kBase + tid];
        s_sb[tid]  = g_sb[q * K_ + kBase + tid];
        s_rn2[tid] = g_rn2[nBase + tid];
        s_sa[tid]  = g_sa[nBase + tid];
        rowKey[tid] = ~0ull;
    }

    const int8_t* gA = g_qres;
    const int8_t* gB = g_qcb + (size_t)q * K_ * D_;

    uint32_t saA[STAGES], saB[STAGES];
#pragma unroll
    for (int s = 0; s < STAGES; s++) {
        saA[s] = (uint32_t)__cvta_generic_to_shared(&sA[s][0]);
        saB[s] = (uint32_t)__cvta_generic_to_shared(&sB[s][0]);
    }

    int c[2][8][4];
#pragma unroll
    for (int i = 0; i < 2; i++)
#pragma unroll
        for (int j = 0; j < 8; j++)
#pragma unroll
            for (int v = 0; v < 4; v++) c[i][j][v] = 0;

    // loader: 128 rows x 64B per tile = 512 x 16B chunks; 2 per thread per matrix
    auto load_tiles = [&](int s, int it) {
#pragma unroll
        for (int u = 0; u < 2; u++) {
            int cidx = tid + 256 * u;
            int r = cidx >> 2, ch = cidx & 3;
            uint32_t off = (uint32_t)(r * 64 + ((ch ^ (r & 3)) << 4));
            cp_async16(saA[s] + off, gA + (size_t)(nBase + r) * D_ + it * BKI + ch * 16);
            cp_async16(saB[s] + off, gB + (size_t)(kBase + r) * D_ + it * BKI + ch * 16);
        }
    };

    load_tiles(0, 0); CP_COMMIT();
    load_tiles(1, 1); CP_COMMIT();

    for (int it = 0; it < NIT; it++) {
        int buf = it % STAGES;
        CP_WAIT1();
        __syncthreads();
        if (it + 2 < NIT) load_tiles((it + 2) % STAGES, it + 2);
        CP_COMMIT();

#pragma unroll
        for (int kk = 0; kk < 2; kk++) {   // two k32 sub-chunks (32B each)
            uint32_t a[2][4], b[8][2];
#pragma unroll
            for (int i = 0; i < 2; i++) {
                int row = warp_m * 32 + i * 16 + (lane & 7) + ((lane >> 3) & 1) * 8;
                int ch = kk * 2 + (lane >> 4);
                uint32_t addr = saA[buf] + (uint32_t)(row * 64 + ((ch ^ (row & 3)) << 4));
                ldsm4(a[i][0], a[i][1], a[i][2], a[i][3], addr);
            }
#pragma unroll
            for (int p = 0; p < 4; p++) {
                int row = warp_n * 64 + p * 16 + (lane & 7) + ((lane >> 4) & 1) * 8;
                int ch = kk * 2 + ((lane >> 3) & 1);
                uint32_t addr = saB[buf] + (uint32_t)(row * 64 + ((ch ^ (row & 3)) << 4));
                ldsm4(b[2 * p][0], b[2 * p][1], b[2 * p + 1][0], b[2 * p + 1][1], addr);
            }
#pragma unroll
            for (int i = 0; i < 2; i++)
#pragma unroll
                for (int j = 0; j < 8; j++)
                    mma_s8(c[i][j], a[i], b[j]);
        }
    }

    // ---- epilogue: dist = rn2 + en2 - 2*sa*sb*idot ; store fp16 ; coarse argmin ----
#pragma unroll
    for (int i = 0; i < 2; i++) {
#pragma unroll
        for (int r2 = 0; r2 < 2; r2++) {
            int rowL = warp_m * 32 + i * 16 + gid + r2 * 8;
            float rn2 = s_rn2[rowL];
            float sc2 = 2.0f * s_sa[rowL];
            unsigned long long best = ~0ull;
            __half* drow = g_disth + (size_t)(nBase + rowL) * K_ + kBase;
#pragma unroll
            for (int j = 0; j < 8; j++) {
                int colL = warp_n * 64 + j * 8 + tig * 2;
                float d0 = rn2 + s_en2[colL] -
                           sc2 * s_sb[colL] * (float)c[i][j][r2 * 2 + 0];
                float d1 = rn2 + s_en2[colL + 1] -
                           sc2 * s_sb[colL + 1] * (float)c[i][j][r2 * 2 + 1];
                *reinterpret_cast<__half2*>(drow + colL) = __floats2half2_rn(d0, d1);
                unsigned kg0 = (unsigned)(kBase + colL);
                unsigned long long k0 =
                    ((unsigned long long)__float_as_uint(d0) << 32) | kg0;
                unsigned long long k1 =
                    ((unsigned long long)__float_as_uint(d1) << 32) | (kg0 + 1);
                if (k0 < best) best = k0;
                if (k1 < best) best = k1;
            }
#pragma unroll
            for (int m = 1; m < 4; m <<= 1) {
                unsigned long long o = __shfl_xor_sync(0xFFFFFFFFu, best, m);
                if (o < best) best = o;
            }
            if (tig == 0) atomicMin(&rowKey[rowL], best);
        }
    }
    __syncthreads();
    if (tid < 128) atomicMin(&g_key[nBase + tid], rowKey[tid]);
}

// ---------------- fixup + update (fused); exact rescore = R1's fmaf chain ----------------
__global__ __launch_bounds__(256)
void fixup_update_kernel(const float* __restrict__ cb, float* __restrict__ xq,
                         float* __restrict__ idx_out, int q) {
    __shared__ alignas(16) float sres[D_];
    __shared__ int s_cand[256];
    __shared__ int s_cnt;
    __shared__ unsigned long long s_best;

    const int r = blockIdx.x;
    const int tid = threadIdx.x;

    if (tid == 0) { s_cnt = 0; s_best = ~0ull; }
    float2 rv = reinterpret_cast<const float2*>(g_res + (size_t)r * D_)[tid];
    sres[2 * tid] = rv.x;
    sres[2 * tid + 1] = rv.y;

    unsigned long long ck = g_key[r];
    float thr = __uint_as_float((unsigned)(ck >> 32)) + 16.0f;
    const __half2* drow = reinterpret_cast<const __half2*>(g_disth + (size_t)r * K_);
    __syncthreads();

#pragma unroll
    for (int i = 0; i < 4; i++) {
        float2 f = __half22float2(drow[tid + i * 256]);
        if (f.x < thr) {
            int p = atomicAdd(&s_cnt, 1);
            if (p < 256) s_cand[p] = (tid + i * 256) * 2;
        }
        if (f.y < thr) {
            int p = atomicAdd(&s_cnt, 1);
            if (p < 256) s_cand[p] = (tid + i * 256) * 2 + 1;
        }
    }
    __syncthreads();
    int nc = min(s_cnt, 256);
    float rn2 = g_rn2[r];
    for (int ci = tid; ci < nc; ci += 256) {
        int k = s_cand[ci];
        const float* crow = cb + (size_t)k * D_;
        float dot = 0.0f;
#pragma unroll 8
        for (int d = 0; d < D_; d++)
            dot = fmaf(sres[d], __ldg(crow + d), dot);
        float dist = (rn2 + g_en2[q * K_ + k]) - 2.0f * dot;
        unsigned long long key =
            ((unsigned long long)__float_as_uint(dist) << 32) | (unsigned)k;
        atomicMin(&s_best, key);
    }
    __syncthreads();
    int kbest = (int)(unsigned)(s_best & 0xFFFFFFFFull);
    if (tid == 0) idx_out[(size_t)r * Q_ + q] = (float)kbest;

    float2 e = reinterpret_cast<const float2*>(cb + (size_t)kbest * D_)[tid];
    reinterpret_cast<float2*>(g_res + (size_t)r * D_)[tid] =
        make_float2(rv.x - e.x, rv.y - e.y);
    float2 xo = reinterpret_cast<float2*>(xq + (size_t)r * D_)[tid];
    reinterpret_cast<float2*>(xq + (size_t)r * D_)[tid] =
        make_float2(xo.x + e.x, xo.y + e.y);
}

// ---------------- finalize mean loss ----------------
__global__ void finalize_kernel(float* __restrict__ loss_out) {
    if (threadIdx.x == 0) {
        double s = 0.0;
        for (int i = 0; i < Q_ * 64; i++) s += g_lossp[i];
        double ml = (s * 1.25 / ((double)N_ * (double)D_)) / (double)Q_;
        *loss_out = (float)ml;
    }
}

// ---------------- launch ----------------
extern "C" void kernel_launch(void* const* d_in, const int* in_sizes, int n_in,
                              void* d_out, int out_size) {
    const float* x = (const float*)d_in[0];
    const float* cbs = (const float*)d_in[1];
    float* out = (float*)d_out;
    float* xq = out;                                  // [N, D]
    float* loss_out = out + (size_t)N_ * D_;          // scalar
    float* idx_out = out + (size_t)N_ * D_ + 1;       // [N, Q] as float

    init_kernel<<<(N_ * D_) / 256, 256>>>(x, xq);       // launch 1
    cbfuse_kernel<<<(Q_ * K_) / 8, 256>>>(cbs);         // launch 2

    for (int q = 0; q < Q_; q++) {
        const float* cb = cbs + (size_t)q * K_ * D_;
        prep_kernel<<<N_ / 8, 256>>>(q);                // launch 3 (q=0)
        dim3 grid(N_ / BM, K_ / BN);
        gemm_dist_kernel<<<grid, 256>>>(q);             // launch 4 (q=0) -> profiled
        fixup_update_kernel<<<N_, 256>>>(cb, xq, idx_out, q);
    }
    prep_kernel<<<N_ / 8, 256>>>(Q_);   // stage-3 loss from final residual
    finalize_kernel<<<1, 32>>>(loss_out);
}

// round 6
// speedup vs baseline: 1.7969x; 1.0046x over previous
#include <cuda_runtime.h>
#include <cstdint>

// Problem constants
#define N_ 32768
#define D_ 512
#define Q_ 4
#define K_ 2048

// GEMM tiling (int8)
#define BM 128
#define BN 128
#define BKI 64
#define NIT (D_ / BKI)   // 8
#define STAGES 3
#define CMAX 96
#define MARGIN 16.0f

// ---------------- device scratch ----------------
__device__ float g_res[N_ * D_];                    // fp32 residual (64 MB)
__device__ int8_t g_qres[N_ * D_];                  // int8 residual (16 MB)
__device__ int8_t g_qcb[Q_ * K_ * D_];              // int8 codebooks (4 MB)
__device__ float g_rn2[N_];
__device__ float g_sa[N_];
__device__ float g_en2[Q_ * K_];
__device__ float g_sb[Q_ * K_];
__device__ unsigned long long g_key[N_];            // global coarse min (dist_bits<<32)|k
__device__ unsigned long long g_cand[(size_t)N_ * CMAX];  // per-row candidates (25 MB)
__device__ int g_ccnt[N_];
__device__ double g_lossp[256];

// ---------------- PTX helpers ----------------
__device__ __forceinline__ void cp_async16(uint32_t saddr, const void* gaddr) {
    asm volatile("cp.async.cg.shared.global [%0], [%1], 16;" :: "r"(saddr), "l"(gaddr));
}
#define CP_COMMIT() asm volatile("cp.async.commit_group;")
#define CP_WAIT1()  asm volatile("cp.async.wait_group 1;")

__device__ __forceinline__ void ldsm4(uint32_t& r0, uint32_t& r1, uint32_t& r2, uint32_t& r3,
                                      uint32_t addr) {
    asm volatile("ldmatrix.sync.aligned.m8n8.x4.shared.b16 {%0,%1,%2,%3}, [%4];"
                 : "=r"(r0), "=r"(r1), "=r"(r2), "=r"(r3) : "r"(addr));
}
__device__ __forceinline__ void mma_s8(int* c, const uint32_t* a, const uint32_t* b) {
    asm volatile(
        "mma.sync.aligned.m16n8k32.row.col.s32.s8.s8.s32 "
        "{%0,%1,%2,%3}, {%4,%5,%6,%7}, {%8,%9}, {%0,%1,%2,%3};"
        : "+r"(c[0]), "+r"(c[1]), "+r"(c[2]), "+r"(c[3])
        : "r"(a[0]), "r"(a[1]), "r"(a[2]), "r"(a[3]), "r"(b[0]), "r"(b[1]));
}

__device__ __forceinline__ int8_t q8(float v, float inv) {
    int t = __float2int_rn(v * inv);
    t = max(-127, min(127, t));
    return (int8_t)t;
}

// ---------------- init ----------------
__global__ void init_kernel(const float* __restrict__ x) {
    int i = blockIdx.x * blockDim.x + threadIdx.x;
    g_res[i] = x[i];
    if (i < 256) g_lossp[i] = 0.0;
    if (i < N_) { g_ccnt[i] = 0; g_key[i] = ~0ull; }
}

// ---------------- codebook: en2 (R1 order) + amax + int8 quant ----------------
__global__ void cbfuse_kernel(const float* __restrict__ cbs) {
    int w = (blockIdx.x * blockDim.x + threadIdx.x) >> 5;
    int lane = threadIdx.x & 31;
    if (w >= Q_ * K_) return;
    const float4* row = reinterpret_cast<const float4*>(cbs + (size_t)w * D_);
    float4 v[4];
    float ss = 0.0f, am = 0.0f;
#pragma unroll
    for (int i = 0; i < 4; i++) {
        v[i] = row[lane + i * 32];
        ss += v[i].x * v[i].x + v[i].y * v[i].y + v[i].z * v[i].z + v[i].w * v[i].w;
        am = fmaxf(am, fmaxf(fmaxf(fabsf(v[i].x), fabsf(v[i].y)),
                             fmaxf(fabsf(v[i].z), fabsf(v[i].w))));
    }
#pragma unroll
    for (int off = 16; off > 0; off >>= 1) {
        ss += __shfl_xor_sync(0xFFFFFFFFu, ss, off);
        am = fmaxf(am, __shfl_xor_sync(0xFFFFFFFFu, am, off));
    }
    float inv = (am > 0.0f) ? 127.0f / am : 0.0f;
    char4* orow = reinterpret_cast<char4*>(g_qcb + (size_t)w * D_);
#pragma unroll
    for (int i = 0; i < 4; i++) {
        char4 c;
        c.x = q8(v[i].x, inv); c.y = q8(v[i].y, inv);
        c.z = q8(v[i].z, inv); c.w = q8(v[i].w, inv);
        orow[lane + i * 32] = c;
    }
    if (lane == 0) { g_en2[w] = ss; g_sb[w] = am / 127.0f; }
}

// ---------------- per-stage prep: rn2 (R1 order) + int8 quant + prev-stage loss ----
__global__ void prep_kernel(int s) {
    int w = (blockIdx.x * blockDim.x + threadIdx.x) >> 5;
    int lane = threadIdx.x & 31;
    if (w >= N_) return;
    const float4* row = reinterpret_cast<const float4*>(g_res + (size_t)w * D_);
    float4 v[4];
    float ss = 0.0f, am = 0.0f;
#pragma unroll
    for (int i = 0; i < 4; i++) {
        v[i] = row[lane + i * 32];
        ss += v[i].x * v[i].x + v[i].y * v[i].y + v[i].z * v[i].z + v[i].w * v[i].w;
        am = fmaxf(am, fmaxf(fmaxf(fabsf(v[i].x), fabsf(v[i].y)),
                             fmaxf(fabsf(v[i].z), fabsf(v[i].w))));
    }
#pragma unroll
    for (int off = 16; off > 0; off >>= 1) {
        ss += __shfl_xor_sync(0xFFFFFFFFu, ss, off);
        am = fmaxf(am, __shfl_xor_sync(0xFFFFFFFFu, am, off));
    }
    float inv = (am > 0.0f) ? 127.0f / am : 0.0f;
    char4* orow = reinterpret_cast<char4*>(g_qres + (size_t)w * D_);
#pragma unroll
    for (int i = 0; i < 4; i++) {
        char4 c;
        c.x = q8(v[i].x, inv); c.y = q8(v[i].y, inv);
        c.z = q8(v[i].z, inv); c.w = q8(v[i].w, inv);
        orow[lane + i * 32] = c;
    }
    if (lane == 0) {
        g_rn2[w] = ss;
        g_sa[w] = am / 127.0f;
        if (s > 0) atomicAdd(&g_lossp[((s - 1) << 6) | (w & 63)], (double)ss);
    }
}

// ---------------- int8 coarse GEMM + candidate selection ----------------
// grid (N_/BM, K_/BN), 256 threads = 8 warps (4m x 2n), warp tile 32x64.
__global__ __launch_bounds__(256, 2)
void gemm_dist_kernel(int q) {
    __shared__ alignas(128) int8_t sA[STAGES][BM * BKI];
    __shared__ alignas(128) int8_t sB[STAGES][BN * BKI];
    __shared__ float s_en2[BN];
    __shared__ float s_rn2[BM];
    __shared__ float s_sa[BM];
    __shared__ float s_sb[BN];
    __shared__ unsigned long long rowKey[BM];

    const int tid = threadIdx.x;
    const int wid = tid >> 5;
    const int lane = tid & 31;
    const int warp_m = wid >> 1;
    const int warp_n = wid & 1;
    const int gid = lane >> 2;
    const int tig = lane & 3;

    const int nBase = blockIdx.x * BM;
    const int kBase = blockIdx.y * BN;

    if (tid < 128) {
        s_en2[tid] = g_en2[q * K_ + kBase + tid];
        s_sb[tid]  = g_sb[q * K_ + kBase + tid];
        s_rn2[tid] = g_rn2[nBase + tid];
        s_sa[tid]  = g_sa[nBase + tid];
        rowKey[tid] = ~0ull;
    }

    const int8_t* gA = g_qres;
    const int8_t* gB = g_qcb + (size_t)q * K_ * D_;

    uint32_t saA[STAGES], saB[STAGES];
#pragma unroll
    for (int s = 0; s < STAGES; s++) {
        saA[s] = (uint32_t)__cvta_generic_to_shared(&sA[s][0]);
        saB[s] = (uint32_t)__cvta_generic_to_shared(&sB[s][0]);
    }

    int c[2][8][4];
#pragma unroll
    for (int i = 0; i < 2; i++)
#pragma unroll
        for (int j = 0; j < 8; j++)
#pragma unroll
            for (int v = 0; v < 4; v++) c[i][j][v] = 0;

    auto load_tiles = [&](int s, int it) {
#pragma unroll
        for (int u = 0; u < 2; u++) {
            int cidx = tid + 256 * u;
            int r = cidx >> 2, ch = cidx & 3;
            uint32_t off = (uint32_t)(r * 64 + ((ch ^ (r & 3)) << 4));
            cp_async16(saA[s] + off, gA + (size_t)(nBase + r) * D_ + it * BKI + ch * 16);
            cp_async16(saB[s] + off, gB + (size_t)(kBase + r) * D_ + it * BKI + ch * 16);
        }
    };

    load_tiles(0, 0); CP_COMMIT();
    load_tiles(1, 1); CP_COMMIT();

    for (int it = 0; it < NIT; it++) {
        int buf = it % STAGES;
        CP_WAIT1();
        __syncthreads();
        if (it + 2 < NIT) load_tiles((it + 2) % STAGES, it + 2);
        CP_COMMIT();

#pragma unroll
        for (int kk = 0; kk < 2; kk++) {
            uint32_t a[2][4], b[8][2];
#pragma unroll
            for (int i = 0; i < 2; i++) {
                int row = warp_m * 32 + i * 16 + (lane & 7) + ((lane >> 3) & 1) * 8;
                int ch = kk * 2 + (lane >> 4);
                uint32_t addr = saA[buf] + (uint32_t)(row * 64 + ((ch ^ (row & 3)) << 4));
                ldsm4(a[i][0], a[i][1], a[i][2], a[i][3], addr);
            }
#pragma unroll
            for (int p = 0; p < 4; p++) {
                int row = warp_n * 64 + p * 16 + (lane & 7) + ((lane >> 4) & 1) * 8;
                int ch = kk * 2 + ((lane >> 3) & 1);
                uint32_t addr = saB[buf] + (uint32_t)(row * 64 + ((ch ^ (row & 3)) << 4));
                ldsm4(b[2 * p][0], b[2 * p][1], b[2 * p + 1][0], b[2 * p + 1][1], addr);
            }
#pragma unroll
            for (int i = 0; i < 2; i++)
#pragma unroll
                for (int j = 0; j < 8; j++)
                    mma_s8(c[i][j], a[i], b[j]);
        }
    }

    // ---- epilogue pass 1: dists (written over c as float bits) + block-local row min ----
#pragma unroll
    for (int i = 0; i < 2; i++) {
#pragma unroll
        for (int r2 = 0; r2 < 2; r2++) {
            int rowL = warp_m * 32 + i * 16 + gid + r2 * 8;
            float rn2 = s_rn2[rowL];
            float sc2 = 2.0f * s_sa[rowL];
            unsigned long long best = ~0ull;
#pragma unroll
            for (int j = 0; j < 8; j++) {
                int colL = warp_n * 64 + j * 8 + tig * 2;
                float d0 = rn2 + s_en2[colL] - sc2 * s_sb[colL] * (float)c[i][j][r2 * 2 + 0];
                float d1 = rn2 + s_en2[colL + 1] - sc2 * s_sb[colL + 1] * (float)c[i][j][r2 * 2 + 1];
                c[i][j][r2 * 2 + 0] = __float_as_int(d0);
                c[i][j][r2 * 2 + 1] = __float_as_int(d1);
                unsigned kg0 = (unsigned)(kBase + colL);
                unsigned long long k0 = ((unsigned long long)__float_as_uint(d0) << 32) | kg0;
                unsigned long long k1 = ((unsigned long long)__float_as_uint(d1) << 32) | (kg0 + 1);
                if (k0 < best) best = k0;
                if (k1 < best) best = k1;
            }
#pragma unroll
            for (int m = 1; m < 4; m <<= 1) {
                unsigned long long o = __shfl_xor_sync(0xFFFFFFFFu, best, m);
                if (o < best) best = o;
            }
            if (tig == 0) atomicMin(&rowKey[rowL], best);
        }
    }
    __syncthreads();
    // global coarse min
    if (tid < 128) atomicMin(&g_key[nBase + tid], rowKey[tid]);

    // ---- epilogue pass 2: append candidates below local min + MARGIN ----
#pragma unroll
    for (int i = 0; i < 2; i++) {
#pragma unroll
        for (int r2 = 0; r2 < 2; r2++) {
            int rowL = warp_m * 32 + i * 16 + gid + r2 * 8;
            int rowG = nBase + rowL;
            float thr = __uint_as_float((unsigned)(rowKey[rowL] >> 32)) + MARGIN;
#pragma unroll
            for (int j = 0; j < 8; j++) {
                int colL = warp_n * 64 + j * 8 + tig * 2;
#pragma unroll
                for (int v = 0; v < 2; v++) {
                    float d = __int_as_float(c[i][j][r2 * 2 + v]);
                    if (d < thr) {
                        int p = atomicAdd(&g_ccnt[rowG], 1);
                        if (p < CMAX)
                            g_cand[(size_t)rowG * CMAX + p] =
                                ((unsigned long long)__float_as_uint(d) << 32) |
                                (unsigned)(kBase + colL + v);
                    }
                }
            }
        }
    }
}

// ---------------- fixup + residual update ----------------
// one block (256 threads) per row; rescore chain byte-identical to R5/R1.
__global__ __launch_bounds__(256)
void fixup_update_kernel(const float* __restrict__ cb, float* __restrict__ idx_out, int q) {
    __shared__ alignas(16) float sres[D_];
    __shared__ unsigned long long s_best;

    const int r = blockIdx.x;
    const int tid = threadIdx.x;

    if (tid == 0) s_best = ~0ull;
    float2 rv = reinterpret_cast<const float2*>(g_res + (size_t)r * D_)[tid];
    sres[2 * tid] = rv.x;
    sres[2 * tid + 1] = rv.y;

    int nc = min(g_ccnt[r], CMAX);
    float thr = __uint_as_float((unsigned)(g_key[r] >> 32)) + MARGIN;
    float rn2 = g_rn2[r];
    __syncthreads();

    for (int ci = tid; ci < nc; ci += 256) {
        unsigned long long cd = g_cand[(size_t)r * CMAX + ci];
        float cdist = __uint_as_float((unsigned)(cd >> 32));
        if (cdist >= thr) continue;
        int k = (int)(unsigned)(cd & 0xFFFFFFFFull);
        const float* crow = cb + (size_t)k * D_;
        float dot = 0.0f;
#pragma unroll 8
        for (int d = 0; d < D_; d++)
            dot = fmaf(sres[d], __ldg(crow + d), dot);
        float dist = (rn2 + g_en2[q * K_ + k]) - 2.0f * dot;
        unsigned long long key =
            ((unsigned long long)__float_as_uint(dist) << 32) | (unsigned)k;
        atomicMin(&s_best, key);
    }
    __syncthreads();
    int kbest = (int)(unsigned)(s_best & 0xFFFFFFFFull);
    if (tid == 0) {
        idx_out[(size_t)r * Q_ + q] = (float)kbest;
        g_ccnt[r] = 0;
        g_key[r] = ~0ull;
    }

    float2 e = reinterpret_cast<const float2*>(cb + (size_t)kbest * D_)[tid];
    reinterpret_cast<float2*>(g_res + (size_t)r * D_)[tid] =
        make_float2(rv.x - e.x, rv.y - e.y);
}

// ---------------- final: xq = x - residual ----------------
__global__ void xq_kernel(const float* __restrict__ x, float* __restrict__ xq) {
    int i = blockIdx.x * blockDim.x + threadIdx.x;
    float4 xv = reinterpret_cast<const float4*>(x)[i];
    float4 rv = reinterpret_cast<const float4*>(g_res)[i];
    reinterpret_cast<float4*>(xq)[i] =
        make_float4(xv.x - rv.x, xv.y - rv.y, xv.z - rv.z, xv.w - rv.w);
}

// ---------------- finalize mean loss ----------------
__global__ void finalize_kernel(float* __restrict__ loss_out) {
    if (threadIdx.x == 0) {
        double s = 0.0;
        for (int i = 0; i < 256; i++) s += g_lossp[i];
        double ml = (s * 1.25 / ((double)N_ * (double)D_)) / (double)Q_;
        *loss_out = (float)ml;
    }
}

// ---------------- launch ----------------
extern "C" void kernel_launch(void* const* d_in, const int* in_sizes, int n_in,
                              void* d_out, int out_size) {
    const float* x = (const float*)d_in[0];
    const float* cbs = (const float*)d_in[1];
    float* out = (float*)d_out;
    float* xq = out;                                  // [N, D]
    float* loss_out = out + (size_t)N_ * D_;          // scalar
    float* idx_out = out + (size_t)N_ * D_ + 1;       // [N, Q] as float

    init_kernel<<<(N_ * D_) / 256, 256>>>(x);
    cbfuse_kernel<<<(Q_ * K_) / 8, 256>>>(cbs);

    for (int q = 0; q < Q_; q++) {
        const float* cb = cbs + (size_t)q * K_ * D_;
        prep_kernel<<<N_ / 8, 256>>>(q);
        dim3 grid(N_ / BM, K_ / BN);
        gemm_dist_kernel<<<grid, 256>>>(q);
        fixup_update_kernel<<<N_, 256>>>(cb, idx_out, q);
    }
    prep_kernel<<<N_ / 8, 256>>>(Q_);   // stage-3 loss from final residual
    xq_kernel<<<(N_ * D_ / 4) / 256, 256>>>(x, xq);
    finalize_kernel<<<1, 32>>>(loss_out);
}

// round 7
// speedup vs baseline: 2.3964x; 1.3337x over previous
#include <cuda_runtime.h>
#include <cstdint>

// Problem constants
#define N_ 32768
#define D_ 512
#define Q_ 4
#define K_ 2048

// GEMM tiling (int8)
#define BM 128
#define BN 128
#define BKI 64
#define NIT (D_ / BKI)   // 8
#define STAGES 3
#define CMAX 96
#define MARGIN 16.0f

// ---------------- device scratch ----------------
__device__ float g_res[N_ * D_];                    // fp32 residual (64 MB)
__device__ int8_t g_qres[N_ * D_];                  // int8 residual (16 MB)
__device__ int8_t g_qcb[Q_ * K_ * D_];              // int8 codebooks (4 MB)
__device__ float g_rn2[N_];
__device__ float g_sa[N_];
__device__ float g_en2[Q_ * K_];
__device__ float g_sb[Q_ * K_];
__device__ unsigned long long g_key[N_];            // global coarse min (dist_bits<<32)|k
__device__ unsigned long long g_cand[(size_t)N_ * CMAX];
__device__ int g_ccnt[N_];
__device__ double g_lossp[256];

// ---------------- PTX helpers ----------------
__device__ __forceinline__ void cp_async16(uint32_t saddr, const void* gaddr) {
    asm volatile("cp.async.cg.shared.global [%0], [%1], 16;" :: "r"(saddr), "l"(gaddr));
}
#define CP_COMMIT() asm volatile("cp.async.commit_group;")
#define CP_WAIT1()  asm volatile("cp.async.wait_group 1;")

__device__ __forceinline__ void ldsm4(uint32_t& r0, uint32_t& r1, uint32_t& r2, uint32_t& r3,
                                      uint32_t addr) {
    asm volatile("ldmatrix.sync.aligned.m8n8.x4.shared.b16 {%0,%1,%2,%3}, [%4];"
                 : "=r"(r0), "=r"(r1), "=r"(r2), "=r"(r3) : "r"(addr));
}
__device__ __forceinline__ void mma_s8(int* c, const uint32_t* a, const uint32_t* b) {
    asm volatile(
        "mma.sync.aligned.m16n8k32.row.col.s32.s8.s8.s32 "
        "{%0,%1,%2,%3}, {%4,%5,%6,%7}, {%8,%9}, {%0,%1,%2,%3};"
        : "+r"(c[0]), "+r"(c[1]), "+r"(c[2]), "+r"(c[3])
        : "r"(a[0]), "r"(a[1]), "r"(a[2]), "r"(a[3]), "r"(b[0]), "r"(b[1]));
}

__device__ __forceinline__ int8_t q8(float v, float inv) {
    int t = __float2int_rn(v * inv);
    t = max(-127, min(127, t));
    return (int8_t)t;
}

// ---------------- init ----------------
__global__ void init_kernel(const float* __restrict__ x) {
    int i = blockIdx.x * blockDim.x + threadIdx.x;
    g_res[i] = x[i];
    if (i < 256) g_lossp[i] = 0.0;
    if (i < N_) { g_ccnt[i] = 0; g_key[i] = ~0ull; }
}

// ---------------- codebook: en2 + amax + int8 quant ----------------
__global__ void cbfuse_kernel(const float* __restrict__ cbs) {
    int w = (blockIdx.x * blockDim.x + threadIdx.x) >> 5;
    int lane = threadIdx.x & 31;
    if (w >= Q_ * K_) return;
    const float4* row = reinterpret_cast<const float4*>(cbs + (size_t)w * D_);
    float4 v[4];
    float ss = 0.0f, am = 0.0f;
#pragma unroll
    for (int i = 0; i < 4; i++) {
        v[i] = row[lane + i * 32];
        ss += v[i].x * v[i].x + v[i].y * v[i].y + v[i].z * v[i].z + v[i].w * v[i].w;
        am = fmaxf(am, fmaxf(fmaxf(fabsf(v[i].x), fabsf(v[i].y)),
                             fmaxf(fabsf(v[i].z), fabsf(v[i].w))));
    }
#pragma unroll
    for (int off = 16; off > 0; off >>= 1) {
        ss += __shfl_xor_sync(0xFFFFFFFFu, ss, off);
        am = fmaxf(am, __shfl_xor_sync(0xFFFFFFFFu, am, off));
    }
    float inv = (am > 0.0f) ? 127.0f / am : 0.0f;
    char4* orow = reinterpret_cast<char4*>(g_qcb + (size_t)w * D_);
#pragma unroll
    for (int i = 0; i < 4; i++) {
        char4 c;
        c.x = q8(v[i].x, inv); c.y = q8(v[i].y, inv);
        c.z = q8(v[i].z, inv); c.w = q8(v[i].w, inv);
        orow[lane + i * 32] = c;
    }
    if (lane == 0) { g_en2[w] = ss; g_sb[w] = am / 127.0f; }
}

// ---------------- stage-0 prep: rn2 + int8 quant of x ----------------
__global__ void prep_kernel() {
    int w = (blockIdx.x * blockDim.x + threadIdx.x) >> 5;
    int lane = threadIdx.x & 31;
    if (w >= N_) return;
    const float4* row = reinterpret_cast<const float4*>(g_res + (size_t)w * D_);
    float4 v[4];
    float ss = 0.0f, am = 0.0f;
#pragma unroll
    for (int i = 0; i < 4; i++) {
        v[i] = row[lane + i * 32];
        ss += v[i].x * v[i].x + v[i].y * v[i].y + v[i].z * v[i].z + v[i].w * v[i].w;
        am = fmaxf(am, fmaxf(fmaxf(fabsf(v[i].x), fabsf(v[i].y)),
                             fmaxf(fabsf(v[i].z), fabsf(v[i].w))));
    }
#pragma unroll
    for (int off = 16; off > 0; off >>= 1) {
        ss += __shfl_xor_sync(0xFFFFFFFFu, ss, off);
        am = fmaxf(am, __shfl_xor_sync(0xFFFFFFFFu, am, off));
    }
    float inv = (am > 0.0f) ? 127.0f / am : 0.0f;
    char4* orow = reinterpret_cast<char4*>(g_qres + (size_t)w * D_);
#pragma unroll
    for (int i = 0; i < 4; i++) {
        char4 c;
        c.x = q8(v[i].x, inv); c.y = q8(v[i].y, inv);
        c.z = q8(v[i].z, inv); c.w = q8(v[i].w, inv);
        orow[lane + i * 32] = c;
    }
    if (lane == 0) { g_rn2[w] = ss; g_sa[w] = am / 127.0f; }
}

// ---------------- int8 coarse GEMM + candidate selection ----------------
__global__ __launch_bounds__(256, 2)
void gemm_dist_kernel(int q) {
    __shared__ alignas(128) int8_t sA[STAGES][BM * BKI];
    __shared__ alignas(128) int8_t sB[STAGES][BN * BKI];
    __shared__ float s_en2[BN];
    __shared__ float s_rn2[BM];
    __shared__ float s_sa[BM];
    __shared__ float s_sb[BN];
    __shared__ unsigned long long rowKey[BM];

    const int tid = threadIdx.x;
    const int wid = tid >> 5;
    const int lane = tid & 31;
    const int warp_m = wid >> 1;
    const int warp_n = wid & 1;
    const int gid = lane >> 2;
    const int tig = lane & 3;

    const int nBase = blockIdx.x * BM;
    const int kBase = blockIdx.y * BN;

    if (tid < 128) {
        s_en2[tid] = g_en2[q * K_ + kBase + tid];
        s_sb[tid]  = g_sb[q * K_ + kBase + tid];
        s_rn2[tid] = g_rn2[nBase + tid];
        s_sa[tid]  = g_sa[nBase + tid];
        rowKey[tid] = ~0ull;
    }

    const int8_t* gA = g_qres;
    const int8_t* gB = g_qcb + (size_t)q * K_ * D_;

    uint32_t saA[STAGES], saB[STAGES];
#pragma unroll
    for (int s = 0; s < STAGES; s++) {
        saA[s] = (uint32_t)__cvta_generic_to_shared(&sA[s][0]);
        saB[s] = (uint32_t)__cvta_generic_to_shared(&sB[s][0]);
    }

    int c[2][8][4];
#pragma unroll
    for (int i = 0; i < 2; i++)
#pragma unroll
        for (int j = 0; j < 8; j++)
#pragma unroll
            for (int v = 0; v < 4; v++) c[i][j][v] = 0;

    auto load_tiles = [&](int s, int it) {
#pragma unroll
        for (int u = 0; u < 2; u++) {
            int cidx = tid + 256 * u;
            int r = cidx >> 2, ch = cidx & 3;
            uint32_t off = (uint32_t)(r * 64 + ((ch ^ (r & 3)) << 4));
            cp_async16(saA[s] + off, gA + (size_t)(nBase + r) * D_ + it * BKI + ch * 16);
            cp_async16(saB[s] + off, gB + (size_t)(kBase + r) * D_ + it * BKI + ch * 16);
        }
    };

    load_tiles(0, 0); CP_COMMIT();
    load_tiles(1, 1); CP_COMMIT();

    for (int it = 0; it < NIT; it++) {
        int buf = it % STAGES;
        CP_WAIT1();
        __syncthreads();
        if (it + 2 < NIT) load_tiles((it + 2) % STAGES, it + 2);
        CP_COMMIT();

#pragma unroll
        for (int kk = 0; kk < 2; kk++) {
            uint32_t a[2][4], b[8][2];
#pragma unroll
            for (int i = 0; i < 2; i++) {
                int row = warp_m * 32 + i * 16 + (lane & 7) + ((lane >> 3) & 1) * 8;
                int ch = kk * 2 + (lane >> 4);
                uint32_t addr = saA[buf] + (uint32_t)(row * 64 + ((ch ^ (row & 3)) << 4));
                ldsm4(a[i][0], a[i][1], a[i][2], a[i][3], addr);
            }
#pragma unroll
            for (int p = 0; p < 4; p++) {
                int row = warp_n * 64 + p * 16 + (lane & 7) + ((lane >> 4) & 1) * 8;
                int ch = kk * 2 + ((lane >> 3) & 1);
                uint32_t addr = saB[buf] + (uint32_t)(row * 64 + ((ch ^ (row & 3)) << 4));
                ldsm4(b[2 * p][0], b[2 * p][1], b[2 * p + 1][0], b[2 * p + 1][1], addr);
            }
#pragma unroll
            for (int i = 0; i < 2; i++)
#pragma unroll
                for (int j = 0; j < 8; j++)
                    mma_s8(c[i][j], a[i], b[j]);
        }
    }

    // ---- epilogue pass 1: dists + block-local row min ----
#pragma unroll
    for (int i = 0; i < 2; i++) {
#pragma unroll
        for (int r2 = 0; r2 < 2; r2++) {
            int rowL = warp_m * 32 + i * 16 + gid + r2 * 8;
            float rn2 = s_rn2[rowL];
            float sc2 = 2.0f * s_sa[rowL];
            unsigned long long best = ~0ull;
#pragma unroll
            for (int j = 0; j < 8; j++) {
                int colL = warp_n * 64 + j * 8 + tig * 2;
                float d0 = rn2 + s_en2[colL] - sc2 * s_sb[colL] * (float)c[i][j][r2 * 2 + 0];
                float d1 = rn2 + s_en2[colL + 1] - sc2 * s_sb[colL + 1] * (float)c[i][j][r2 * 2 + 1];
                c[i][j][r2 * 2 + 0] = __float_as_int(d0);
                c[i][j][r2 * 2 + 1] = __float_as_int(d1);
                unsigned kg0 = (unsigned)(kBase + colL);
                unsigned long long k0 = ((unsigned long long)__float_as_uint(d0) << 32) | kg0;
                unsigned long long k1 = ((unsigned long long)__float_as_uint(d1) << 32) | (kg0 + 1);
                if (k0 < best) best = k0;
                if (k1 < best) best = k1;
            }
#pragma unroll
            for (int m = 1; m < 4; m <<= 1) {
                unsigned long long o = __shfl_xor_sync(0xFFFFFFFFu, best, m);
                if (o < best) best = o;
            }
            if (tig == 0) atomicMin(&rowKey[rowL], best);
        }
    }
    __syncthreads();
    if (tid < 128) atomicMin(&g_key[nBase + tid], rowKey[tid]);

    // ---- epilogue pass 2: append candidates below local min + MARGIN ----
#pragma unroll
    for (int i = 0; i < 2; i++) {
#pragma unroll
        for (int r2 = 0; r2 < 2; r2++) {
            int rowL = warp_m * 32 + i * 16 + gid + r2 * 8;
            int rowG = nBase + rowL;
            float thr = __uint_as_float((unsigned)(rowKey[rowL] >> 32)) + MARGIN;
#pragma unroll
            for (int j = 0; j < 8; j++) {
                int colL = warp_n * 64 + j * 8 + tig * 2;
#pragma unroll
                for (int v = 0; v < 2; v++) {
                    float d = __int_as_float(c[i][j][r2 * 2 + v]);
                    if (d < thr) {
                        int p = atomicAdd(&g_ccnt[rowG], 1);
                        if (p < CMAX)
                            g_cand[(size_t)rowG * CMAX + p] =
                                ((unsigned long long)__float_as_uint(d) << 32) |
                                (unsigned)(kBase + colL + v);
                    }
                }
            }
        }
    }
}

// ---------------- fixup + full row update (fused prep) ----------------
// one block (128 threads = 4 warps) per row
__global__ __launch_bounds__(128)
void fixup_update_kernel(const float* __restrict__ cb, float* __restrict__ idx_out, int q) {
    __shared__ alignas(16) float sres[D_];
    __shared__ alignas(16) float scb[4][D_];
    __shared__ unsigned long long s_best;
    __shared__ float s_ss[4], s_am[4], s_bcast[2];

    const int r = blockIdx.x;
    const int tid = threadIdx.x;
    const int wid = tid >> 5;
    const int lane = tid & 31;

    if (tid == 0) s_best = ~0ull;
    float4 rv = reinterpret_cast<const float4*>(g_res + (size_t)r * D_)[tid];
    reinterpret_cast<float4*>(sres)[tid] = rv;

    unsigned long long gk = g_key[r];
    int nc = min(g_ccnt[r], CMAX);
    float thr = __uint_as_float((unsigned)(gk >> 32)) + MARGIN;
    float rn2 = g_rn2[r];
    __syncthreads();

    int kbest;
    if (nc <= 1) {
        // only candidate within margin is the coarse min -> provably exact best
        kbest = (int)(unsigned)(gk & 0xFFFFFFFFull);
    } else {
        for (int base = 0; base < nc; base += 4) {
            int ci = base + wid;
            if (ci < nc) {
                unsigned long long cd = g_cand[(size_t)r * CMAX + ci];
                float cdist = __uint_as_float((unsigned)(cd >> 32));
                if (cdist < thr) {
                    int k = (int)(unsigned)(cd & 0xFFFFFFFFull);
                    const float4* crow = reinterpret_cast<const float4*>(cb + (size_t)k * D_);
#pragma unroll
                    for (int i = 0; i < 4; i++)
                        reinterpret_cast<float4*>(scb[wid])[lane + i * 32] = crow[lane + i * 32];
                    __syncwarp();
                    if (lane == 0) {
                        // exact rescore: ascending-d sequential fmaf chain (matches R1)
                        float dot = 0.0f;
#pragma unroll 8
                        for (int d = 0; d < D_; d++)
                            dot = fmaf(sres[d], scb[wid][d], dot);
                        float dist = (rn2 + g_en2[q * K_ + k]) - 2.0f * dot;
                        unsigned long long key =
                            ((unsigned long long)__float_as_uint(dist) << 32) | (unsigned)k;
                        atomicMin(&s_best, key);
                    }
                    __syncwarp();
                }
            }
        }
        __syncthreads();
        kbest = (int)(unsigned)(s_best & 0xFFFFFFFFull);
    }

    // residual update
    float4 e = reinterpret_cast<const float4*>(cb + (size_t)kbest * D_)[tid];
    float4 nr = make_float4(rv.x - e.x, rv.y - e.y, rv.z - e.z, rv.w - e.w);
    reinterpret_cast<float4*>(g_res + (size_t)r * D_)[tid] = nr;

    // block reduce rn2' and amax
    float ss = nr.x * nr.x + nr.y * nr.y + nr.z * nr.z + nr.w * nr.w;
    float am = fmaxf(fmaxf(fabsf(nr.x), fabsf(nr.y)), fmaxf(fabsf(nr.z), fabsf(nr.w)));
#pragma unroll
    for (int off = 16; off > 0; off >>= 1) {
        ss += __shfl_xor_sync(0xFFFFFFFFu, ss, off);
        am = fmaxf(am, __shfl_xor_sync(0xFFFFFFFFu, am, off));
    }
    if (lane == 0) { s_ss[wid] = ss; s_am[wid] = am; }
    __syncthreads();
    if (tid == 0) {
        float t1 = s_ss[0] + s_ss[1] + s_ss[2] + s_ss[3];
        float t2 = fmaxf(fmaxf(s_am[0], s_am[1]), fmaxf(s_am[2], s_am[3]));
        s_bcast[0] = t1;
        s_bcast[1] = t2;
        g_rn2[r] = t1;
        g_sa[r] = t2 / 127.0f;
        g_ccnt[r] = 0;
        g_key[r] = ~0ull;
        idx_out[(size_t)r * Q_ + q] = (float)kbest;
        atomicAdd(&g_lossp[(q << 6) | (r & 63)], (double)t1);
    }
    __syncthreads();
    float amT = s_bcast[1];
    float inv = (amT > 0.0f) ? 127.0f / amT : 0.0f;
    char4 qc;
    qc.x = q8(nr.x, inv); qc.y = q8(nr.y, inv);
    qc.z = q8(nr.z, inv); qc.w = q8(nr.w, inv);
    reinterpret_cast<char4*>(g_qres + (size_t)r * D_)[tid] = qc;
}

// ---------------- final: xq = x - residual ----------------
__global__ void xq_kernel(const float* __restrict__ x, float* __restrict__ xq) {
    int i = blockIdx.x * blockDim.x + threadIdx.x;
    float4 xv = reinterpret_cast<const float4*>(x)[i];
    float4 rv = reinterpret_cast<const float4*>(g_res)[i];
    reinterpret_cast<float4*>(xq)[i] =
        make_float4(xv.x - rv.x, xv.y - rv.y, xv.z - rv.z, xv.w - rv.w);
}

// ---------------- finalize mean loss ----------------
__global__ void finalize_kernel(float* __restrict__ loss_out) {
    if (threadIdx.x == 0) {
        double s = 0.0;
        for (int i = 0; i < 256; i++) s += g_lossp[i];
        double ml = (s * 1.25 / ((double)N_ * (double)D_)) / (double)Q_;
        *loss_out = (float)ml;
    }
}

// ---------------- launch ----------------
extern "C" void kernel_launch(void* const* d_in, const int* in_sizes, int n_in,
                              void* d_out, int out_size) {
    const float* x = (const float*)d_in[0];
    const float* cbs = (const float*)d_in[1];
    float* out = (float*)d_out;
    float* xq = out;                                  // [N, D]
    float* loss_out = out + (size_t)N_ * D_;          // scalar
    float* idx_out = out + (size_t)N_ * D_ + 1;       // [N, Q] as float

    init_kernel<<<(N_ * D_) / 256, 256>>>(x);
    cbfuse_kernel<<<(Q_ * K_) / 8, 256>>>(cbs);
    prep_kernel<<<N_ / 8, 256>>>();

    for (int q = 0; q < Q_; q++) {
        const float* cb = cbs + (size_t)q * K_ * D_;
        dim3 grid(N_ / BM, K_ / BN);
        gemm_dist_kernel<<<grid, 256>>>(q);
        fixup_update_kernel<<<N_, 128>>>(cb, idx_out, q);
    }
    xq_kernel<<<(N_ * D_ / 4) / 256, 256>>>(x, xq);
    finalize_kernel<<<1, 32>>>(loss_out);
}

// round 8
// speedup vs baseline: 2.4523x; 1.0233x over previous
#include <cuda_runtime.h>
#include <cstdint>

// Problem constants
#define N_ 32768
#define D_ 512
#define Q_ 4
#define K_ 2048

// GEMM tiling (int8)
#define BM 128
#define BN 128
#define BKI 64
#define NIT (D_ / BKI)   // 8
#define STAGES 3
#define CMAX 128
#define MARGIN 16.0f

// ---------------- device scratch ----------------
__device__ float g_res[N_ * D_];                    // fp32 residual (64 MB)
__device__ int8_t g_qres[N_ * D_];                  // int8 residual (16 MB)
__device__ int8_t g_qcb[Q_ * K_ * D_];              // int8 codebooks (4 MB)
__device__ float g_rn2[N_];
__device__ float g_sa[N_];
__device__ float g_en2[Q_ * K_];
__device__ float g_sb[Q_ * K_];
__device__ unsigned long long g_key[N_];            // global coarse min (dist_bits<<32)|k
__device__ unsigned long long g_cand[(size_t)N_ * CMAX];
__device__ int g_ccnt[N_];
__device__ double g_lossp[256];

// ---------------- PTX helpers ----------------
__device__ __forceinline__ void cp_async16(uint32_t saddr, const void* gaddr) {
    asm volatile("cp.async.cg.shared.global [%0], [%1], 16;" :: "r"(saddr), "l"(gaddr));
}
#define CP_COMMIT() asm volatile("cp.async.commit_group;")
#define CP_WAIT1()  asm volatile("cp.async.wait_group 1;")

__device__ __forceinline__ void ldsm4(uint32_t& r0, uint32_t& r1, uint32_t& r2, uint32_t& r3,
                                      uint32_t addr) {
    asm volatile("ldmatrix.sync.aligned.m8n8.x4.shared.b16 {%0,%1,%2,%3}, [%4];"
                 : "=r"(r0), "=r"(r1), "=r"(r2), "=r"(r3) : "r"(addr));
}
__device__ __forceinline__ void mma_s8(int* c, const uint32_t* a, const uint32_t* b) {
    asm volatile(
        "mma.sync.aligned.m16n8k32.row.col.s32.s8.s8.s32 "
        "{%0,%1,%2,%3}, {%4,%5,%6,%7}, {%8,%9}, {%0,%1,%2,%3};"
        : "+r"(c[0]), "+r"(c[1]), "+r"(c[2]), "+r"(c[3])
        : "r"(a[0]), "r"(a[1]), "r"(a[2]), "r"(a[3]), "r"(b[0]), "r"(b[1]));
}

__device__ __forceinline__ int8_t q8(float v, float inv) {
    int t = __float2int_rn(v * inv);
    t = max(-127, min(127, t));
    return (int8_t)t;
}

// ---------------- prep (fused init): res = x, rn2, amax, int8 quant ----------------
__global__ void prep_kernel(const float* __restrict__ x) {
    int w = (blockIdx.x * blockDim.x + threadIdx.x) >> 5;
    int lane = threadIdx.x & 31;
    if (w >= N_) return;
    const float4* row = reinterpret_cast<const float4*>(x + (size_t)w * D_);
    float4* rrow = reinterpret_cast<float4*>(g_res + (size_t)w * D_);
    float4 v[4];
    float ss = 0.0f, am = 0.0f;
#pragma unroll
    for (int i = 0; i < 4; i++) {
        v[i] = row[lane + i * 32];
        rrow[lane + i * 32] = v[i];
        ss += v[i].x * v[i].x + v[i].y * v[i].y + v[i].z * v[i].z + v[i].w * v[i].w;
        am = fmaxf(am, fmaxf(fmaxf(fabsf(v[i].x), fabsf(v[i].y)),
                             fmaxf(fabsf(v[i].z), fabsf(v[i].w))));
    }
#pragma unroll
    for (int off = 16; off > 0; off >>= 1) {
        ss += __shfl_xor_sync(0xFFFFFFFFu, ss, off);
        am = fmaxf(am, __shfl_xor_sync(0xFFFFFFFFu, am, off));
    }
    float inv = (am > 0.0f) ? 127.0f / am : 0.0f;
    char4* orow = reinterpret_cast<char4*>(g_qres + (size_t)w * D_);
#pragma unroll
    for (int i = 0; i < 4; i++) {
        char4 c;
        c.x = q8(v[i].x, inv); c.y = q8(v[i].y, inv);
        c.z = q8(v[i].z, inv); c.w = q8(v[i].w, inv);
        orow[lane + i * 32] = c;
    }
    if (lane == 0) { g_rn2[w] = ss; g_sa[w] = am / 127.0f; }
}

// ---------------- codebook: en2 + amax + int8 quant + global resets ----------------
__global__ void cbfuse_kernel(const float* __restrict__ cbs) {
    int gidx = blockIdx.x * blockDim.x + threadIdx.x;
    if (gidx < N_) { g_ccnt[gidx] = 0; g_key[gidx] = ~0ull; }
    if (gidx < 256) g_lossp[gidx] = 0.0;
    int w = gidx >> 5;
    int lane = threadIdx.x & 31;
    if (w >= Q_ * K_) return;
    const float4* row = reinterpret_cast<const float4*>(cbs + (size_t)w * D_);
    float4 v[4];
    float ss = 0.0f, am = 0.0f;
#pragma unroll
    for (int i = 0; i < 4; i++) {
        v[i] = row[lane + i * 32];
        ss += v[i].x * v[i].x + v[i].y * v[i].y + v[i].z * v[i].z + v[i].w * v[i].w;
        am = fmaxf(am, fmaxf(fmaxf(fabsf(v[i].x), fabsf(v[i].y)),
                             fmaxf(fabsf(v[i].z), fabsf(v[i].w))));
    }
#pragma unroll
    for (int off = 16; off > 0; off >>= 1) {
        ss += __shfl_xor_sync(0xFFFFFFFFu, ss, off);
        am = fmaxf(am, __shfl_xor_sync(0xFFFFFFFFu, am, off));
    }
    float inv = (am > 0.0f) ? 127.0f / am : 0.0f;
    char4* orow = reinterpret_cast<char4*>(g_qcb + (size_t)w * D_);
#pragma unroll
    for (int i = 0; i < 4; i++) {
        char4 c;
        c.x = q8(v[i].x, inv); c.y = q8(v[i].y, inv);
        c.z = q8(v[i].z, inv); c.w = q8(v[i].w, inv);
        orow[lane + i * 32] = c;
    }
    if (lane == 0) { g_en2[w] = ss; g_sb[w] = am / 127.0f; }
}

// ---------------- int8 coarse GEMM + candidate selection ----------------
__global__ __launch_bounds__(256, 2)
void gemm_dist_kernel(int q) {
    __shared__ alignas(128) int8_t sA[STAGES][BM * BKI];
    __shared__ alignas(128) int8_t sB[STAGES][BN * BKI];
    __shared__ float s_en2[BN];
    __shared__ float s_rn2[BM];
    __shared__ float s_sa[BM];
    __shared__ float s_sb[BN];
    __shared__ unsigned long long rowKey[BM];

    const int tid = threadIdx.x;
    const int wid = tid >> 5;
    const int lane = tid & 31;
    const int warp_m = wid >> 1;
    const int warp_n = wid & 1;
    const int gid = lane >> 2;
    const int tig = lane & 3;

    const int nBase = blockIdx.x * BM;
    const int kBase = blockIdx.y * BN;

    if (tid < 128) {
        s_en2[tid] = g_en2[q * K_ + kBase + tid];
        s_sb[tid]  = g_sb[q * K_ + kBase + tid];
        s_rn2[tid] = g_rn2[nBase + tid];
        s_sa[tid]  = g_sa[nBase + tid];
        rowKey[tid] = ~0ull;
    }

    const int8_t* gA = g_qres;
    const int8_t* gB = g_qcb + (size_t)q * K_ * D_;

    uint32_t saA[STAGES], saB[STAGES];
#pragma unroll
    for (int s = 0; s < STAGES; s++) {
        saA[s] = (uint32_t)__cvta_generic_to_shared(&sA[s][0]);
        saB[s] = (uint32_t)__cvta_generic_to_shared(&sB[s][0]);
    }

    int c[2][8][4];
#pragma unroll
    for (int i = 0; i < 2; i++)
#pragma unroll
        for (int j = 0; j < 8; j++)
#pragma unroll
            for (int v = 0; v < 4; v++) c[i][j][v] = 0;

    auto load_tiles = [&](int s, int it) {
#pragma unroll
        for (int u = 0; u < 2; u++) {
            int cidx = tid + 256 * u;
            int r = cidx >> 2, ch = cidx & 3;
            uint32_t off = (uint32_t)(r * 64 + ((ch ^ (r & 3)) << 4));
            cp_async16(saA[s] + off, gA + (size_t)(nBase + r) * D_ + it * BKI + ch * 16);
            cp_async16(saB[s] + off, gB + (size_t)(kBase + r) * D_ + it * BKI + ch * 16);
        }
    };

    load_tiles(0, 0); CP_COMMIT();
    load_tiles(1, 1); CP_COMMIT();

    for (int it = 0; it < NIT; it++) {
        int buf = it % STAGES;
        CP_WAIT1();
        __syncthreads();
        if (it + 2 < NIT) load_tiles((it + 2) % STAGES, it + 2);
        CP_COMMIT();

#pragma unroll
        for (int kk = 0; kk < 2; kk++) {
            uint32_t a[2][4], b[8][2];
#pragma unroll
            for (int i = 0; i < 2; i++) {
                int row = warp_m * 32 + i * 16 + (lane & 7) + ((lane >> 3) & 1) * 8;
                int ch = kk * 2 + (lane >> 4);
                uint32_t addr = saA[buf] + (uint32_t)(row * 64 + ((ch ^ (row & 3)) << 4));
                ldsm4(a[i][0], a[i][1], a[i][2], a[i][3], addr);
            }
#pragma unroll
            for (int p = 0; p < 4; p++) {
                int row = warp_n * 64 + p * 16 + (lane & 7) + ((lane >> 4) & 1) * 8;
                int ch = kk * 2 + ((lane >> 3) & 1);
                uint32_t addr = saB[buf] + (uint32_t)(row * 64 + ((ch ^ (row & 3)) << 4));
                ldsm4(b[2 * p][0], b[2 * p][1], b[2 * p + 1][0], b[2 * p + 1][1], addr);
            }
#pragma unroll
            for (int i = 0; i < 2; i++)
#pragma unroll
                for (int j = 0; j < 8; j++)
                    mma_s8(c[i][j], a[i], b[j]);
        }
    }

    // ---- epilogue pass 1: dists + block-local row min ----
#pragma unroll
    for (int i = 0; i < 2; i++) {
#pragma unroll
        for (int r2 = 0; r2 < 2; r2++) {
            int rowL = warp_m * 32 + i * 16 + gid + r2 * 8;
            float rn2 = s_rn2[rowL];
            float sc2 = 2.0f * s_sa[rowL];
            unsigned long long best = ~0ull;
#pragma unroll
            for (int j = 0; j < 8; j++) {
                int colL = warp_n * 64 + j * 8 + tig * 2;
                float d0 = rn2 + s_en2[colL] - sc2 * s_sb[colL] * (float)c[i][j][r2 * 2 + 0];
                float d1 = rn2 + s_en2[colL + 1] - sc2 * s_sb[colL + 1] * (float)c[i][j][r2 * 2 + 1];
                c[i][j][r2 * 2 + 0] = __float_as_int(d0);
                c[i][j][r2 * 2 + 1] = __float_as_int(d1);
                unsigned kg0 = (unsigned)(kBase + colL);
                unsigned long long k0 = ((unsigned long long)__float_as_uint(d0) << 32) | kg0;
                unsigned long long k1 = ((unsigned long long)__float_as_uint(d1) << 32) | (kg0 + 1);
                if (k0 < best) best = k0;
                if (k1 < best) best = k1;
            }
#pragma unroll
            for (int m = 1; m < 4; m <<= 1) {
                unsigned long long o = __shfl_xor_sync(0xFFFFFFFFu, best, m);
                if (o < best) best = o;
            }
            if (tig == 0) atomicMin(&rowKey[rowL], best);
        }
    }
    __syncthreads();
    // global coarse min; tighten local threshold with running global knowledge
    if (tid < 128) {
        unsigned long long mine = rowKey[tid];
        unsigned long long old = atomicMin(&g_key[nBase + tid], mine);
        rowKey[tid] = (old < mine) ? old : mine;
    }
    __syncthreads();

    // ---- epilogue pass 2: append candidates below (best-known min) + MARGIN ----
#pragma unroll
    for (int i = 0; i < 2; i++) {
#pragma unroll
        for (int r2 = 0; r2 < 2; r2++) {
            int rowL = warp_m * 32 + i * 16 + gid + r2 * 8;
            int rowG = nBase + rowL;
            float thr = __uint_as_float((unsigned)(rowKey[rowL] >> 32)) + MARGIN;
#pragma unroll
            for (int j = 0; j < 8; j++) {
                int colL = warp_n * 64 + j * 8 + tig * 2;
#pragma unroll
                for (int v = 0; v < 2; v++) {
                    float d = __int_as_float(c[i][j][r2 * 2 + v]);
                    if (d < thr) {
                        int p = atomicAdd(&g_ccnt[rowG], 1);
                        if (p < CMAX)
                            g_cand[(size_t)rowG * CMAX + p] =
                                ((unsigned long long)__float_as_uint(d) << 32) |
                                (unsigned)(kBase + colL + v);
                    }
                }
            }
        }
    }
}

// ---------------- fixup + full row update, warp-per-row ----------------
// 8 warps per block, 1 row each; no block-wide syncs.
__global__ __launch_bounds__(256)
void fixup_update_kernel(const float* __restrict__ cb, const float* __restrict__ x,
                         float* __restrict__ xq, float* __restrict__ idx_out, int q) {
    __shared__ alignas(16) float sres[8][D_];
    __shared__ alignas(16) float scb[8][D_];

    const int tid = threadIdx.x;
    const int wid = tid >> 5;
    const int lane = tid & 31;
    const int r = blockIdx.x * 8 + wid;

    const float4* res4 = reinterpret_cast<const float4*>(g_res + (size_t)r * D_);
    float4 rv[4];
#pragma unroll
    for (int i = 0; i < 4; i++) {
        rv[i] = res4[lane + i * 32];
        reinterpret_cast<float4*>(sres[wid])[lane + i * 32] = rv[i];
    }
    unsigned long long gk = g_key[r];
    int nc = min(g_ccnt[r], CMAX);
    float thr = __uint_as_float((unsigned)(gk >> 32)) + MARGIN;
    float rn2 = g_rn2[r];
    __syncwarp();

    int kbest;
    if (nc <= 1) {
        // sole in-margin candidate is the coarse min -> provably the exact best
        kbest = (int)(unsigned)(gk & 0xFFFFFFFFull);
    } else {
        unsigned long long best = ~0ull;
        for (int ci = 0; ci < nc; ci++) {
            unsigned long long cd = g_cand[(size_t)r * CMAX + ci];
            float cdist = __uint_as_float((unsigned)(cd >> 32));
            if (cdist >= thr) continue;
            int k = (int)(unsigned)(cd & 0xFFFFFFFFull);
            const float4* crow = reinterpret_cast<const float4*>(cb + (size_t)k * D_);
#pragma unroll
            for (int i = 0; i < 4; i++)
                reinterpret_cast<float4*>(scb[wid])[lane + i * 32] = crow[lane + i * 32];
            __syncwarp();
            if (lane == 0) {
                // exact rescore: ascending-d sequential fmaf chain (matches R1)
                float dot = 0.0f;
#pragma unroll 8
                for (int d = 0; d < D_; d++)
                    dot = fmaf(sres[wid][d], scb[wid][d], dot);
                float dist = (rn2 + g_en2[q * K_ + k]) - 2.0f * dot;
                unsigned long long key =
                    ((unsigned long long)__float_as_uint(dist) << 32) | (unsigned)k;
                if (key < best) best = key;
            }
            __syncwarp();
        }
        best = __shfl_sync(0xFFFFFFFFu, best, 0);
        kbest = (int)(unsigned)(best & 0xFFFFFFFFull);
    }

    // residual update + reductions (R1 warp order)
    const float4* e4 = reinterpret_cast<const float4*>(cb + (size_t)kbest * D_);
    float4 nr[4];
    float ss = 0.0f, am = 0.0f;
#pragma unroll
    for (int i = 0; i < 4; i++) {
        float4 e = e4[lane + i * 32];
        nr[i] = make_float4(rv[i].x - e.x, rv[i].y - e.y, rv[i].z - e.z, rv[i].w - e.w);
        ss += nr[i].x * nr[i].x + nr[i].y * nr[i].y + nr[i].z * nr[i].z + nr[i].w * nr[i].w;
        am = fmaxf(am, fmaxf(fmaxf(fabsf(nr[i].x), fabsf(nr[i].y)),
                             fmaxf(fabsf(nr[i].z), fabsf(nr[i].w))));
    }
#pragma unroll
    for (int off = 16; off > 0; off >>= 1) {
        ss += __shfl_xor_sync(0xFFFFFFFFu, ss, off);
        am = fmaxf(am, __shfl_xor_sync(0xFFFFFFFFu, am, off));
    }

    if (q < Q_ - 1) {
        // write fp32 + int8 residual for the next stage
        float4* orow = reinterpret_cast<float4*>(g_res + (size_t)r * D_);
        float inv = (am > 0.0f) ? 127.0f / am : 0.0f;
        char4* qrow = reinterpret_cast<char4*>(g_qres + (size_t)r * D_);
#pragma unroll
        for (int i = 0; i < 4; i++) {
            orow[lane + i * 32] = nr[i];
            char4 c;
            c.x = q8(nr[i].x, inv); c.y = q8(nr[i].y, inv);
            c.z = q8(nr[i].z, inv); c.w = q8(nr[i].w, inv);
            qrow[lane + i * 32] = c;
        }
        if (lane == 0) {
            g_rn2[r] = ss;
            g_sa[r] = am / 127.0f;
            g_ccnt[r] = 0;
            g_key[r] = ~0ull;
        }
    } else {
        // last stage: emit xq = x - residual_final directly; no scratch writes
        const float4* x4 = reinterpret_cast<const float4*>(x + (size_t)r * D_);
        float4* o4 = reinterpret_cast<float4*>(xq + (size_t)r * D_);
#pragma unroll
        for (int i = 0; i < 4; i++) {
            float4 xv = x4[lane + i * 32];
            o4[lane + i * 32] = make_float4(xv.x - nr[i].x, xv.y - nr[i].y,
                                            xv.z - nr[i].z, xv.w - nr[i].w);
        }
    }
    if (lane == 0) {
        idx_out[(size_t)r * Q_ + q] = (float)kbest;
        atomicAdd(&g_lossp[(q << 6) | (r & 63)], (double)ss);
    }
}

// ---------------- finalize mean loss ----------------
__global__ void finalize_kernel(float* __restrict__ loss_out) {
    if (threadIdx.x == 0) {
        double s = 0.0;
        for (int i = 0; i < 256; i++) s += g_lossp[i];
        double ml = (s * 1.25 / ((double)N_ * (double)D_)) / (double)Q_;
        *loss_out = (float)ml;
    }
}

// ---------------- launch ----------------
extern "C" void kernel_launch(void* const* d_in, const int* in_sizes, int n_in,
                              void* d_out, int out_size) {
    const float* x = (const float*)d_in[0];
    const float* cbs = (const float*)d_in[1];
    float* out = (float*)d_out;
    float* xq = out;                                  // [N, D]
    float* loss_out = out + (size_t)N_ * D_;          // scalar
    float* idx_out = out + (size_t)N_ * D_ + 1;       // [N, Q] as float

    prep_kernel<<<N_ / 8, 256>>>(x);
    cbfuse_kernel<<<(Q_ * K_) / 8, 256>>>(cbs);

    for (int q = 0; q < Q_; q++) {
        const float* cb = cbs + (size_t)q * K_ * D_;
        dim3 grid(N_ / BM, K_ / BN);
        gemm_dist_kernel<<<grid, 256>>>(q);
        fixup_update_kernel<<<N_ / 8, 256>>>(cb, x, xq, idx_out, q);
    }
    finalize_kernel<<<1, 32>>>(loss_out);
}

// round 9
// speedup vs baseline: 2.7602x; 1.1255x over previous
#include <cuda_runtime.h>
#include <cstdint>

// Problem constants
#define N_ 32768
#define D_ 512
#define Q_ 4
#define K_ 2048

// GEMM tiling (int8)
#define BM 128
#define BN 128
#define BKI 64
#define NIT (D_ / BKI)   // 8
#define STAGES 3
#define CMAX 128
#define MARGIN 16.0f

// ---------------- device scratch ----------------
__device__ float g_res[N_ * D_];                    // fp32 residual (64 MB)
__device__ int8_t g_qres[N_ * D_];                  // int8 residual (16 MB)
__device__ int8_t g_qcb[Q_ * K_ * D_];              // int8 codebooks (4 MB)
__device__ float g_rn2[N_];
__device__ float g_sa[N_];
__device__ float g_en2[Q_ * K_];
__device__ float g_sb[Q_ * K_];
__device__ unsigned long long g_key[N_];            // global coarse min (dist_bits<<32)|k
__device__ unsigned long long g_cand[(size_t)N_ * CMAX];
__device__ int g_ccnt[N_];
__device__ double g_lossp[256];

// ---------------- PTX helpers ----------------
__device__ __forceinline__ void cp_async16(uint32_t saddr, const void* gaddr) {
    asm volatile("cp.async.cg.shared.global [%0], [%1], 16;" :: "r"(saddr), "l"(gaddr));
}
#define CP_COMMIT() asm volatile("cp.async.commit_group;")
#define CP_WAIT1()  asm volatile("cp.async.wait_group 1;")

__device__ __forceinline__ void ldsm4(uint32_t& r0, uint32_t& r1, uint32_t& r2, uint32_t& r3,
                                      uint32_t addr) {
    asm volatile("ldmatrix.sync.aligned.m8n8.x4.shared.b16 {%0,%1,%2,%3}, [%4];"
                 : "=r"(r0), "=r"(r1), "=r"(r2), "=r"(r3) : "r"(addr));
}
__device__ __forceinline__ void mma_s8(int* c, const uint32_t* a, const uint32_t* b) {
    asm volatile(
        "mma.sync.aligned.m16n8k32.row.col.s32.s8.s8.s32 "
        "{%0,%1,%2,%3}, {%4,%5,%6,%7}, {%8,%9}, {%0,%1,%2,%3};"
        : "+r"(c[0]), "+r"(c[1]), "+r"(c[2]), "+r"(c[3])
        : "r"(a[0]), "r"(a[1]), "r"(a[2]), "r"(a[3]), "r"(b[0]), "r"(b[1]));
}

__device__ __forceinline__ int8_t q8(float v, float inv) {
    int t = __float2int_rn(v * inv);
    t = max(-127, min(127, t));
    return (int8_t)t;
}

// ---------------- prep (fused init): res = x, rn2, amax, int8 quant ----------------
__global__ void prep_kernel(const float* __restrict__ x) {
    int w = (blockIdx.x * blockDim.x + threadIdx.x) >> 5;
    int lane = threadIdx.x & 31;
    if (w >= N_) return;
    const float4* row = reinterpret_cast<const float4*>(x + (size_t)w * D_);
    float4* rrow = reinterpret_cast<float4*>(g_res + (size_t)w * D_);
    float4 v[4];
    float ss = 0.0f, am = 0.0f;
#pragma unroll
    for (int i = 0; i < 4; i++) {
        v[i] = row[lane + i * 32];
        rrow[lane + i * 32] = v[i];
        ss += v[i].x * v[i].x + v[i].y * v[i].y + v[i].z * v[i].z + v[i].w * v[i].w;
        am = fmaxf(am, fmaxf(fmaxf(fabsf(v[i].x), fabsf(v[i].y)),
                             fmaxf(fabsf(v[i].z), fabsf(v[i].w))));
    }
#pragma unroll
    for (int off = 16; off > 0; off >>= 1) {
        ss += __shfl_xor_sync(0xFFFFFFFFu, ss, off);
        am = fmaxf(am, __shfl_xor_sync(0xFFFFFFFFu, am, off));
    }
    float inv = (am > 0.0f) ? 127.0f / am : 0.0f;
    char4* orow = reinterpret_cast<char4*>(g_qres + (size_t)w * D_);
#pragma unroll
    for (int i = 0; i < 4; i++) {
        char4 c;
        c.x = q8(v[i].x, inv); c.y = q8(v[i].y, inv);
        c.z = q8(v[i].z, inv); c.w = q8(v[i].w, inv);
        orow[lane + i * 32] = c;
    }
    if (lane == 0) { g_rn2[w] = ss; g_sa[w] = am / 127.0f; }
}

// ---------------- codebook: en2 + amax + int8 quant + global resets ----------------
__global__ void cbfuse_kernel(const float* __restrict__ cbs) {
    int gidx = blockIdx.x * blockDim.x + threadIdx.x;
    if (gidx < N_) { g_ccnt[gidx] = 0; g_key[gidx] = ~0ull; }
    if (gidx < 256) g_lossp[gidx] = 0.0;
    int w = gidx >> 5;
    int lane = threadIdx.x & 31;
    if (w >= Q_ * K_) return;
    const float4* row = reinterpret_cast<const float4*>(cbs + (size_t)w * D_);
    float4 v[4];
    float ss = 0.0f, am = 0.0f;
#pragma unroll
    for (int i = 0; i < 4; i++) {
        v[i] = row[lane + i * 32];
        ss += v[i].x * v[i].x + v[i].y * v[i].y + v[i].z * v[i].z + v[i].w * v[i].w;
        am = fmaxf(am, fmaxf(fmaxf(fabsf(v[i].x), fabsf(v[i].y)),
                             fmaxf(fabsf(v[i].z), fabsf(v[i].w))));
    }
#pragma unroll
    for (int off = 16; off > 0; off >>= 1) {
        ss += __shfl_xor_sync(0xFFFFFFFFu, ss, off);
        am = fmaxf(am, __shfl_xor_sync(0xFFFFFFFFu, am, off));
    }
    float inv = (am > 0.0f) ? 127.0f / am : 0.0f;
    char4* orow = reinterpret_cast<char4*>(g_qcb + (size_t)w * D_);
#pragma unroll
    for (int i = 0; i < 4; i++) {
        char4 c;
        c.x = q8(v[i].x, inv); c.y = q8(v[i].y, inv);
        c.z = q8(v[i].z, inv); c.w = q8(v[i].w, inv);
        orow[lane + i * 32] = c;
    }
    if (lane == 0) { g_en2[w] = ss; g_sb[w] = am / 127.0f; }
}

// ---------------- int8 coarse GEMM + candidate selection ----------------
__global__ __launch_bounds__(256, 2)
void gemm_dist_kernel(int q) {
    __shared__ alignas(128) int8_t sA[STAGES][BM * BKI];
    __shared__ alignas(128) int8_t sB[STAGES][BN * BKI];
    __shared__ float s_en2[BN];
    __shared__ float s_rn2[BM];
    __shared__ float s_sa[BM];
    __shared__ float s_sb[BN];
    __shared__ unsigned long long rowKey[BM];

    const int tid = threadIdx.x;
    const int wid = tid >> 5;
    const int lane = tid & 31;
    const int warp_m = wid >> 1;
    const int warp_n = wid & 1;
    const int gid = lane >> 2;
    const int tig = lane & 3;

    const int nBase = blockIdx.x * BM;
    const int kBase = blockIdx.y * BN;

    if (tid < 128) {
        s_en2[tid] = g_en2[q * K_ + kBase + tid];
        s_sb[tid]  = g_sb[q * K_ + kBase + tid];
        s_rn2[tid] = g_rn2[nBase + tid];
        s_sa[tid]  = g_sa[nBase + tid];
        rowKey[tid] = ~0ull;
    }

    const int8_t* gA = g_qres;
    const int8_t* gB = g_qcb + (size_t)q * K_ * D_;

    uint32_t saA[STAGES], saB[STAGES];
#pragma unroll
    for (int s = 0; s < STAGES; s++) {
        saA[s] = (uint32_t)__cvta_generic_to_shared(&sA[s][0]);
        saB[s] = (uint32_t)__cvta_generic_to_shared(&sB[s][0]);
    }

    int c[2][8][4];
#pragma unroll
    for (int i = 0; i < 2; i++)
#pragma unroll
        for (int j = 0; j < 8; j++)
#pragma unroll
            for (int v = 0; v < 4; v++) c[i][j][v] = 0;

    auto load_tiles = [&](int s, int it) {
#pragma unroll
        for (int u = 0; u < 2; u++) {
            int cidx = tid + 256 * u;
            int r = cidx >> 2, ch = cidx & 3;
            uint32_t off = (uint32_t)(r * 64 + ((ch ^ (r & 3)) << 4));
            cp_async16(saA[s] + off, gA + (size_t)(nBase + r) * D_ + it * BKI + ch * 16);
            cp_async16(saB[s] + off, gB + (size_t)(kBase + r) * D_ + it * BKI + ch * 16);
        }
    };

    load_tiles(0, 0); CP_COMMIT();
    load_tiles(1, 1); CP_COMMIT();

    for (int it = 0; it < NIT; it++) {
        int buf = it % STAGES;
        CP_WAIT1();
        __syncthreads();
        if (it + 2 < NIT) load_tiles((it + 2) % STAGES, it + 2);
        CP_COMMIT();

#pragma unroll
        for (int kk = 0; kk < 2; kk++) {
            uint32_t a[2][4], b[8][2];
#pragma unroll
            for (int i = 0; i < 2; i++) {
                int row = warp_m * 32 + i * 16 + (lane & 7) + ((lane >> 3) & 1) * 8;
                int ch = kk * 2 + (lane >> 4);
                uint32_t addr = saA[buf] + (uint32_t)(row * 64 + ((ch ^ (row & 3)) << 4));
                ldsm4(a[i][0], a[i][1], a[i][2], a[i][3], addr);
            }
#pragma unroll
            for (int p = 0; p < 4; p++) {
                int row = warp_n * 64 + p * 16 + (lane & 7) + ((lane >> 4) & 1) * 8;
                int ch = kk * 2 + ((lane >> 3) & 1);
                uint32_t addr = saB[buf] + (uint32_t)(row * 64 + ((ch ^ (row & 3)) << 4));
                ldsm4(b[2 * p][0], b[2 * p][1], b[2 * p + 1][0], b[2 * p + 1][1], addr);
            }
#pragma unroll
            for (int i = 0; i < 2; i++)
#pragma unroll
                for (int j = 0; j < 8; j++)
                    mma_s8(c[i][j], a[i], b[j]);
        }
    }

    // ---- epilogue pass 1: dists + block-local row min ----
#pragma unroll
    for (int i = 0; i < 2; i++) {
#pragma unroll
        for (int r2 = 0; r2 < 2; r2++) {
            int rowL = warp_m * 32 + i * 16 + gid + r2 * 8;
            float rn2 = s_rn2[rowL];
            float sc2 = 2.0f * s_sa[rowL];
            unsigned long long best = ~0ull;
#pragma unroll
            for (int j = 0; j < 8; j++) {
                int colL = warp_n * 64 + j * 8 + tig * 2;
                float d0 = rn2 + s_en2[colL] - sc2 * s_sb[colL] * (float)c[i][j][r2 * 2 + 0];
                float d1 = rn2 + s_en2[colL + 1] - sc2 * s_sb[colL + 1] * (float)c[i][j][r2 * 2 + 1];
                c[i][j][r2 * 2 + 0] = __float_as_int(d0);
                c[i][j][r2 * 2 + 1] = __float_as_int(d1);
                unsigned kg0 = (unsigned)(kBase + colL);
                unsigned long long k0 = ((unsigned long long)__float_as_uint(d0) << 32) | kg0;
                unsigned long long k1 = ((unsigned long long)__float_as_uint(d1) << 32) | (kg0 + 1);
                if (k0 < best) best = k0;
                if (k1 < best) best = k1;
            }
#pragma unroll
            for (int m = 1; m < 4; m <<= 1) {
                unsigned long long o = __shfl_xor_sync(0xFFFFFFFFu, best, m);
                if (o < best) best = o;
            }
            if (tig == 0) atomicMin(&rowKey[rowL], best);
        }
    }
    __syncthreads();
    // global coarse min; tighten local threshold with running global knowledge
    if (tid < 128) {
        unsigned long long mine = rowKey[tid];
        unsigned long long old = atomicMin(&g_key[nBase + tid], mine);
        rowKey[tid] = (old < mine) ? old : mine;
    }
    __syncthreads();

    // ---- epilogue pass 2: append candidates below (best-known min) + MARGIN ----
#pragma unroll
    for (int i = 0; i < 2; i++) {
#pragma unroll
        for (int r2 = 0; r2 < 2; r2++) {
            int rowL = warp_m * 32 + i * 16 + gid + r2 * 8;
            int rowG = nBase + rowL;
            float thr = __uint_as_float((unsigned)(rowKey[rowL] >> 32)) + MARGIN;
#pragma unroll
            for (int j = 0; j < 8; j++) {
                int colL = warp_n * 64 + j * 8 + tig * 2;
#pragma unroll
                for (int v = 0; v < 2; v++) {
                    float d = __int_as_float(c[i][j][r2 * 2 + v]);
                    if (d < thr) {
                        int p = atomicAdd(&g_ccnt[rowG], 1);
                        if (p < CMAX)
                            g_cand[(size_t)rowG * CMAX + p] =
                                ((unsigned long long)__float_as_uint(d) << 32) |
                                (unsigned)(kBase + colL + v);
                    }
                }
            }
        }
    }
}

// ---------------- fixup + full row update, warp-per-row ----------------
// 4 warps per block, 1 row each; rescore chains run on up to 4 lanes in parallel.
__global__ __launch_bounds__(128)
void fixup_update_kernel(const float* __restrict__ cb, const float* __restrict__ x,
                         float* __restrict__ xq, float* __restrict__ idx_out, int q) {
    __shared__ alignas(16) float sres[4][D_];
    __shared__ alignas(16) float scb[4][4][516];   // padded stride: conflict-free chains

    const int tid = threadIdx.x;
    const int wid = tid >> 5;
    const int lane = tid & 31;
    const int r = blockIdx.x * 4 + wid;

    const float4* res4 = reinterpret_cast<const float4*>(g_res + (size_t)r * D_);
    float4 rv[4];
#pragma unroll
    for (int i = 0; i < 4; i++) rv[i] = res4[lane + i * 32];

    unsigned long long gk = g_key[r];
    int nc = min(g_ccnt[r], CMAX);
    float thr = __uint_as_float((unsigned)(gk >> 32)) + MARGIN;
    float rn2 = g_rn2[r];

    int kbest;
    if (nc <= 1) {
        // sole in-margin candidate is the coarse min -> provably the exact best
        kbest = (int)(unsigned)(gk & 0xFFFFFFFFull);
    } else {
#pragma unroll
        for (int i = 0; i < 4; i++)
            reinterpret_cast<float4*>(sres[wid])[lane + i * 32] = rv[i];
        __syncwarp();

        unsigned long long best = ~0ull;
        for (int base = 0; base < nc; base += 4) {
            // lanes 0..3 hold one candidate each
            unsigned long long cd = ~0ull;
            if (lane < 4 && base + lane < nc)
                cd = g_cand[(size_t)r * CMAX + base + lane];
            float cdist = __uint_as_float((unsigned)(cd >> 32));
            int kc = (int)(unsigned)(cd & 0xFFFFFFFFull);
            bool valid = (lane < 4) && (base + lane < nc) && (cdist < thr);
            unsigned vm = __ballot_sync(0xFFFFFFFFu, valid);

            // stage valid candidate rows into smem (whole warp per row)
#pragma unroll
            for (int j = 0; j < 4; j++) {
                if (!((vm >> j) & 1)) continue;
                int kj = __shfl_sync(0xFFFFFFFFu, kc, j);
                const float4* crow = reinterpret_cast<const float4*>(cb + (size_t)kj * D_);
                float4* dst = reinterpret_cast<float4*>(&scb[wid][j][0]);
#pragma unroll
                for (int i = 0; i < 4; i++) dst[lane + i * 32] = crow[lane + i * 32];
            }
            __syncwarp();

            if (valid) {
                // exact rescore: ascending-d sequential fmaf chain (matches R1 bits)
                float dot = 0.0f;
                const float* sr = sres[wid];
                const float* sc = scb[wid][lane];
#pragma unroll 8
                for (int d = 0; d < D_; d++)
                    dot = fmaf(sr[d], sc[d], dot);
                float dist = (rn2 + g_en2[q * K_ + kc]) - 2.0f * dot;
                unsigned long long key =
                    ((unsigned long long)__float_as_uint(dist) << 32) | (unsigned)kc;
                if (key < best) best = key;
            }
            __syncwarp();
        }
        // warp-wide min (only lanes 0..3 contributed; others hold ~0)
#pragma unroll
        for (int m = 16; m > 0; m >>= 1) {
            unsigned long long o = __shfl_xor_sync(0xFFFFFFFFu, best, m);
            if (o < best) best = o;
        }
        kbest = (int)(unsigned)(best & 0xFFFFFFFFull);
    }

    // residual update + reductions
    const float4* e4 = reinterpret_cast<const float4*>(cb + (size_t)kbest * D_);
    float4 nr[4];
    float ss = 0.0f, am = 0.0f;
#pragma unroll
    for (int i = 0; i < 4; i++) {
        float4 e = e4[lane + i * 32];
        nr[i] = make_float4(rv[i].x - e.x, rv[i].y - e.y, rv[i].z - e.z, rv[i].w - e.w);
        ss += nr[i].x * nr[i].x + nr[i].y * nr[i].y + nr[i].z * nr[i].z + nr[i].w * nr[i].w;
        am = fmaxf(am, fmaxf(fmaxf(fabsf(nr[i].x), fabsf(nr[i].y)),
                             fmaxf(fabsf(nr[i].z), fabsf(nr[i].w))));
    }
#pragma unroll
    for (int off = 16; off > 0; off >>= 1) {
        ss += __shfl_xor_sync(0xFFFFFFFFu, ss, off);
        am = fmaxf(am, __shfl_xor_sync(0xFFFFFFFFu, am, off));
    }

    if (q < Q_ - 1) {
        float4* orow = reinterpret_cast<float4*>(g_res + (size_t)r * D_);
        float inv = (am > 0.0f) ? 127.0f / am : 0.0f;
        char4* qrow = reinterpret_cast<char4*>(g_qres + (size_t)r * D_);
#pragma unroll
        for (int i = 0; i < 4; i++) {
            orow[lane + i * 32] = nr[i];
            char4 c;
            c.x = q8(nr[i].x, inv); c.y = q8(nr[i].y, inv);
            c.z = q8(nr[i].z, inv); c.w = q8(nr[i].w, inv);
            qrow[lane + i * 32] = c;
        }
        if (lane == 0) {
            g_rn2[r] = ss;
            g_sa[r] = am / 127.0f;
            g_ccnt[r] = 0;
            g_key[r] = ~0ull;
        }
    } else {
        // last stage: emit xq = x - residual_final directly
        const float4* x4 = reinterpret_cast<const float4*>(x + (size_t)r * D_);
        float4* o4 = reinterpret_cast<float4*>(xq + (size_t)r * D_);
#pragma unroll
        for (int i = 0; i < 4; i++) {
            float4 xv = x4[lane + i * 32];
            o4[lane + i * 32] = make_float4(xv.x - nr[i].x, xv.y - nr[i].y,
                                            xv.z - nr[i].z, xv.w - nr[i].w);
        }
    }
    if (lane == 0) {
        idx_out[(size_t)r * Q_ + q] = (float)kbest;
        atomicAdd(&g_lossp[(q << 6) | (r & 63)], (double)ss);
    }
}

// ---------------- finalize mean loss ----------------
__global__ void finalize_kernel(float* __restrict__ loss_out) {
    if (threadIdx.x == 0) {
        double s = 0.0;
        for (int i = 0; i < 256; i++) s += g_lossp[i];
        double ml = (s * 1.25 / ((double)N_ * (double)D_)) / (double)Q_;
        *loss_out = (float)ml;
    }
}

// ---------------- launch ----------------
extern "C" void kernel_launch(void* const* d_in, const int* in_sizes, int n_in,
                              void* d_out, int out_size) {
    const float* x = (const float*)d_in[0];
    const float* cbs = (const float*)d_in[1];
    float* out = (float*)d_out;
    float* xq = out;                                  // [N, D]
    float* loss_out = out + (size_t)N_ * D_;          // scalar
    float* idx_out = out + (size_t)N_ * D_ + 1;       // [N, Q] as float

    prep_kernel<<<N_ / 8, 256>>>(x);
    cbfuse_kernel<<<(Q_ * K_) / 8, 256>>>(cbs);

    for (int q = 0; q < Q_; q++) {
        const float* cb = cbs + (size_t)q * K_ * D_;
        dim3 grid(N_ / BM, K_ / BN);
        gemm_dist_kernel<<<grid, 256>>>(q);
        fixup_update_kernel<<<N_ / 4, 128>>>(cb, x, xq, idx_out, q);
    }
    finalize_kernel<<<1, 32>>>(loss_out);
}